// round 1
// baseline (speedup 1.0000x reference)
#include <cuda_runtime.h>

#define S_  512      // B*T segments
#define P_  1024     // points per segment
#define C_  32       // input channels
#define D1  64       // pre hidden 1
#define D2  128      // pre hidden 2
#define D3  256      // between / out width
#define NPTS (S_ * P_)

// ---------------- global scratch (static __device__, no runtime alloc) ----------------
__device__ float g_h2[(size_t)NPTS * D2];   // masked h2      (256 MB)
__device__ float g_h3[(size_t)NPTS * D3];   // h3             (512 MB)
__device__ float g_c[S_ * D3];              // per-segment pooled@W3_bot + b3
__device__ float g_feat[S_ * D3];           // segment max of h4
__device__ int   g_valid[S_];               // any-point-valid flag

__device__ __forceinline__ void atomicMaxF_nonneg(float* addr, float v) {
    // valid only for non-negative floats (IEEE order == int order there)
    atomicMax((int*)addr, __float_as_int(v));
}

// =====================================================================================
// Kernel A: per-segment fused pre-MLP.
//   x(1024x32) -> h1(64) -> h2(128), relu+mask, store h2 to scratch,
//   pooled = max_p h2, c = b3 + pooled @ W3[128:,:], valid flag, zero g_feat.
// grid = 512 CTAs (one per segment), 256 threads.
// =====================================================================================
__global__ void __launch_bounds__(256, 1)
kA(const float* __restrict__ x, const int* __restrict__ mask,
   const float* __restrict__ W1, const float* __restrict__ b1,
   const float* __restrict__ W2, const float* __restrict__ b2,
   const float* __restrict__ W3, const float* __restrict__ b3)
{
    extern __shared__ float sm[];
    float* W1s = sm;                   // 32*64   = 2048
    float* W2s = W1s + 32 * 64;        // 64*128  = 8192
    float* b1s = W2s + 64 * 128;       // 64
    float* b2s = b1s + 64;             // 128
    float* xs  = b2s + 128;            // [32][132] transposed x tile
    float* h1s = xs + 32 * 132;        // [64][132] transposed h1 tile
    float* pool = h1s + 64 * 132;      // 128
    int*   ms  = (int*)(pool + 128);   // 128 mask words for tile
    int*   vf  = ms + 128;             // 1

    const int t = threadIdx.x;
    const int s = blockIdx.x;

    for (int i = t; i < 32 * 64;  i += 256) W1s[i] = W1[i];
    for (int i = t; i < 64 * 128; i += 256) W2s[i] = W2[i];
    if (t < 64)  b1s[t] = b1[t];
    if (t < 128) { b2s[t] = b2[t]; pool[t] = 0.f; }
    if (t == 0)  *vf = 0;
    g_feat[s * D3 + t] = 0.f;   // pre-zero feat for kernel C's atomicMax

    const int tx = t & 15, ty = t >> 4;
    const int r0 = ty * 8;       // row group (points)
    const int c1 = tx * 4;       // h1 col group
    const int c2 = tx * 8;       // h2 col group

    float pmax[8];
    #pragma unroll
    for (int j = 0; j < 8; j++) pmax[j] = 0.f;

    for (int tile = 0; tile < 8; ++tile) {
        const int p0 = tile * 128;
        __syncthreads();                      // protect smem reuse
        // ---- load x tile transposed: xs[c][p] ----
        {
            const int p = t >> 1;
            const int coff = (t & 1) * 16;
            const float* gx = x + (size_t)(s * P_ + p0 + p) * C_ + coff;
            #pragma unroll
            for (int q = 0; q < 4; q++) {
                float4 v = *(const float4*)(gx + 4 * q);
                xs[(coff + 4 * q + 0) * 132 + p] = v.x;
                xs[(coff + 4 * q + 1) * 132 + p] = v.y;
                xs[(coff + 4 * q + 2) * 132 + p] = v.z;
                xs[(coff + 4 * q + 3) * 132 + p] = v.w;
            }
        }
        if (t < 128) {
            int mv = (mask[s * P_ + p0 + t] != 0);   // works for fp32 or int32 0/1
            ms[t] = mv;
            if (mv) atomicOr(vf, 1);
        }
        __syncthreads();
        // ---- h1 = relu(x @ W1 + b1): M=128, N=64, K=32; micro 8x4 ----
        {
            float acc[8][4];
            #pragma unroll
            for (int i = 0; i < 8; i++)
                #pragma unroll
                for (int j = 0; j < 4; j++) acc[i][j] = b1s[c1 + j];
            #pragma unroll 8
            for (int k = 0; k < 32; k++) {
                float4 a0 = *(const float4*)&xs[k * 132 + r0];
                float4 a1 = *(const float4*)&xs[k * 132 + r0 + 4];
                float4 bv = *(const float4*)&W1s[k * 64 + c1];
                float a[8] = {a0.x, a0.y, a0.z, a0.w, a1.x, a1.y, a1.z, a1.w};
                float b[4] = {bv.x, bv.y, bv.z, bv.w};
                #pragma unroll
                for (int i = 0; i < 8; i++)
                    #pragma unroll
                    for (int j = 0; j < 4; j++) acc[i][j] += a[i] * b[j];
            }
            #pragma unroll
            for (int j = 0; j < 4; j++) {
                float4 v0, v1;
                v0.x = fmaxf(acc[0][j], 0.f); v0.y = fmaxf(acc[1][j], 0.f);
                v0.z = fmaxf(acc[2][j], 0.f); v0.w = fmaxf(acc[3][j], 0.f);
                v1.x = fmaxf(acc[4][j], 0.f); v1.y = fmaxf(acc[5][j], 0.f);
                v1.z = fmaxf(acc[6][j], 0.f); v1.w = fmaxf(acc[7][j], 0.f);
                *(float4*)&h1s[(c1 + j) * 132 + r0]     = v0;
                *(float4*)&h1s[(c1 + j) * 132 + r0 + 4] = v1;
            }
        }
        __syncthreads();
        // ---- h2 = relu(h1 @ W2 + b2), mask, store, track max: M=128,N=128,K=64 ----
        {
            float acc[8][8];
            #pragma unroll
            for (int i = 0; i < 8; i++)
                #pragma unroll
                for (int j = 0; j < 8; j++) acc[i][j] = b2s[c2 + j];
            #pragma unroll 4
            for (int k = 0; k < 64; k++) {
                float4 a0 = *(const float4*)&h1s[k * 132 + r0];
                float4 a1 = *(const float4*)&h1s[k * 132 + r0 + 4];
                float4 b0v = *(const float4*)&W2s[k * 128 + c2];
                float4 b1v = *(const float4*)&W2s[k * 128 + c2 + 4];
                float a[8] = {a0.x, a0.y, a0.z, a0.w, a1.x, a1.y, a1.z, a1.w};
                float b[8] = {b0v.x, b0v.y, b0v.z, b0v.w, b1v.x, b1v.y, b1v.z, b1v.w};
                #pragma unroll
                for (int i = 0; i < 8; i++)
                    #pragma unroll
                    for (int j = 0; j < 8; j++) acc[i][j] += a[i] * b[j];
            }
            #pragma unroll
            for (int i = 0; i < 8; i++) {
                const int p = r0 + i;
                const int keep = ms[p];
                float v[8];
                #pragma unroll
                for (int j = 0; j < 8; j++) {
                    float z = fmaxf(acc[i][j], 0.f);
                    z = keep ? z : 0.f;
                    v[j] = z;
                    pmax[j] = fmaxf(pmax[j], z);
                }
                float* gp = g_h2 + (size_t)(s * P_ + p0 + p) * D2 + c2;
                *(float4*)gp       = make_float4(v[0], v[1], v[2], v[3]);
                *(float4*)(gp + 4) = make_float4(v[4], v[5], v[6], v[7]);
            }
        }
    }
    // ---- combine pooled max across threads ----
    #pragma unroll
    for (int j = 0; j < 8; j++) atomicMaxF_nonneg(&pool[c2 + j], pmax[j]);
    __syncthreads();
    // ---- c = b3 + pooled @ W3[128:, :]  (one output per thread) ----
    {
        float acc = b3[t];
        #pragma unroll 4
        for (int k = 0; k < 128; k++)
            acc += pool[k] * W3[(size_t)(128 + k) * D3 + t];
        g_c[s * D3 + t] = acc;
    }
    if (t == 0) g_valid[s] = *vf;
}

// =====================================================================================
// Kernel B: h3 = relu(h2 @ W3_top + c).  M=512K, N=256, K=128.
// Block tile 128x128, K slabs of 64, micro 8x8. grid = (2 n-tiles, 4096 m-tiles).
// =====================================================================================
__global__ void __launch_bounds__(256, 1)
kB(const float* __restrict__ W3)
{
    extern __shared__ float sm[];
    float* As = sm;             // [64][132] transposed A slab
    float* Bs = As + 64 * 132;  // [64][128]

    const int t  = threadIdx.x;
    const int n0 = blockIdx.x * 128;
    const int m0 = blockIdx.y * 128;
    const int s  = m0 >> 10;
    const int tx = t & 15, ty = t >> 4;
    const int r0 = ty * 8, c0 = tx * 8;

    float acc[8][8];
    #pragma unroll
    for (int i = 0; i < 8; i++)
        #pragma unroll
        for (int j = 0; j < 8; j++) acc[i][j] = 0.f;

    for (int k0 = 0; k0 < 128; k0 += 64) {
        __syncthreads();
        {   // A slab (transpose): rows m0..m0+127, k in [k0,k0+64)
            const int row = t >> 1;
            const int kc  = (t & 1) * 32;
            const float* ga = g_h2 + (size_t)(m0 + row) * D2 + k0 + kc;
            #pragma unroll
            for (int q = 0; q < 8; q++) {
                float4 v = *(const float4*)(ga + 4 * q);
                As[(kc + 4 * q + 0) * 132 + row] = v.x;
                As[(kc + 4 * q + 1) * 132 + row] = v.y;
                As[(kc + 4 * q + 2) * 132 + row] = v.z;
                As[(kc + 4 * q + 3) * 132 + row] = v.w;
            }
        }
        {   // B slab: W3 rows k0..k0+63, cols n0..n0+127
            const int k  = t >> 2;
            const int cc = (t & 3) * 32;
            const float* gb = W3 + (size_t)(k0 + k) * D3 + n0 + cc;
            float* sb = Bs + k * 128 + cc;
            #pragma unroll
            for (int q = 0; q < 8; q++)
                *(float4*)(sb + 4 * q) = *(const float4*)(gb + 4 * q);
        }
        __syncthreads();
        #pragma unroll 4
        for (int k = 0; k < 64; k++) {
            float4 a0 = *(const float4*)&As[k * 132 + r0];
            float4 a1 = *(const float4*)&As[k * 132 + r0 + 4];
            float4 b0v = *(const float4*)&Bs[k * 128 + c0];
            float4 b1v = *(const float4*)&Bs[k * 128 + c0 + 4];
            float a[8] = {a0.x, a0.y, a0.z, a0.w, a1.x, a1.y, a1.z, a1.w};
            float b[8] = {b0v.x, b0v.y, b0v.z, b0v.w, b1v.x, b1v.y, b1v.z, b1v.w};
            #pragma unroll
            for (int i = 0; i < 8; i++)
                #pragma unroll
                for (int j = 0; j < 8; j++) acc[i][j] += a[i] * b[j];
        }
    }
    float cv[8];
    #pragma unroll
    for (int j = 0; j < 8; j++) cv[j] = g_c[s * D3 + n0 + c0 + j];
    #pragma unroll
    for (int i = 0; i < 8; i++) {
        float v[8];
        #pragma unroll
        for (int j = 0; j < 8; j++) v[j] = fmaxf(acc[i][j] + cv[j], 0.f);
        float* gp = g_h3 + (size_t)(m0 + r0 + i) * D3 + n0 + c0;
        *(float4*)gp       = make_float4(v[0], v[1], v[2], v[3]);
        *(float4*)(gp + 4) = make_float4(v[4], v[5], v[6], v[7]);
    }
}

// =====================================================================================
// Kernel C: h4 = relu(h3 @ W4 + b4), mask, column-max per tile -> atomicMax g_feat.
// M=512K, N=256, K=256 (4 slabs of 64). Same tiling as kB. h4 never stored.
// =====================================================================================
__global__ void __launch_bounds__(256, 1)
kC(const float* __restrict__ W4, const float* __restrict__ b4,
   const int* __restrict__ mask)
{
    extern __shared__ float sm[];
    float* As = sm;
    float* Bs = As + 64 * 132;
    float* colmax = Bs + 64 * 128;      // 128
    int*   ms = (int*)(colmax + 128);   // 128

    const int t  = threadIdx.x;
    const int n0 = blockIdx.x * 128;
    const int m0 = blockIdx.y * 128;
    const int s  = m0 >> 10;
    const int tx = t & 15, ty = t >> 4;
    const int r0 = ty * 8, c0 = tx * 8;

    if (t < 128) { colmax[t] = 0.f; ms[t] = (mask[m0 + t] != 0); }

    float acc[8][8];
    #pragma unroll
    for (int i = 0; i < 8; i++)
        #pragma unroll
        for (int j = 0; j < 8; j++) acc[i][j] = 0.f;

    for (int k0 = 0; k0 < 256; k0 += 64) {
        __syncthreads();
        {   // A slab from g_h3 (row stride 256)
            const int row = t >> 1;
            const int kc  = (t & 1) * 32;
            const float* ga = g_h3 + (size_t)(m0 + row) * D3 + k0 + kc;
            #pragma unroll
            for (int q = 0; q < 8; q++) {
                float4 v = *(const float4*)(ga + 4 * q);
                As[(kc + 4 * q + 0) * 132 + row] = v.x;
                As[(kc + 4 * q + 1) * 132 + row] = v.y;
                As[(kc + 4 * q + 2) * 132 + row] = v.z;
                As[(kc + 4 * q + 3) * 132 + row] = v.w;
            }
        }
        {   // B slab from W4
            const int k  = t >> 2;
            const int cc = (t & 3) * 32;
            const float* gb = W4 + (size_t)(k0 + k) * D3 + n0 + cc;
            float* sb = Bs + k * 128 + cc;
            #pragma unroll
            for (int q = 0; q < 8; q++)
                *(float4*)(sb + 4 * q) = *(const float4*)(gb + 4 * q);
        }
        __syncthreads();
        #pragma unroll 4
        for (int k = 0; k < 64; k++) {
            float4 a0 = *(const float4*)&As[k * 132 + r0];
            float4 a1 = *(const float4*)&As[k * 132 + r0 + 4];
            float4 b0v = *(const float4*)&Bs[k * 128 + c0];
            float4 b1v = *(const float4*)&Bs[k * 128 + c0 + 4];
            float a[8] = {a0.x, a0.y, a0.z, a0.w, a1.x, a1.y, a1.z, a1.w};
            float b[8] = {b0v.x, b0v.y, b0v.z, b0v.w, b1v.x, b1v.y, b1v.z, b1v.w};
            #pragma unroll
            for (int i = 0; i < 8; i++)
                #pragma unroll
                for (int j = 0; j < 8; j++) acc[i][j] += a[i] * b[j];
        }
    }
    float bv[8];
    #pragma unroll
    for (int j = 0; j < 8; j++) bv[j] = b4[n0 + c0 + j];
    float tm[8];
    #pragma unroll
    for (int j = 0; j < 8; j++) tm[j] = 0.f;
    #pragma unroll
    for (int i = 0; i < 8; i++) {
        const int keep = ms[r0 + i];
        #pragma unroll
        for (int j = 0; j < 8; j++) {
            float z = fmaxf(acc[i][j] + bv[j], 0.f);
            z = keep ? z : 0.f;
            tm[j] = fmaxf(tm[j], z);
        }
    }
    #pragma unroll
    for (int j = 0; j < 8; j++) atomicMaxF_nonneg(&colmax[c0 + j], tm[j]);
    __syncthreads();
    if (t < 128)
        atomicMax((int*)&g_feat[s * D3 + n0 + t], __float_as_int(colmax[t]));
}

// =====================================================================================
// Kernel D: per-segment out MLP. out = relu(feat@Wo1+bo1)@Wo2 + bo2, zero if !valid.
// grid = 512, 256 threads (one output feature per thread).
// =====================================================================================
__global__ void __launch_bounds__(256, 1)
kD(const float* __restrict__ Wo1, const float* __restrict__ bo1,
   const float* __restrict__ Wo2, const float* __restrict__ bo2,
   float* __restrict__ out)
{
    __shared__ float fs[D3], t1[D3];
    const int t = threadIdx.x, s = blockIdx.x;
    fs[t] = g_feat[s * D3 + t];
    __syncthreads();
    float a = bo1[t];
    #pragma unroll 8
    for (int k = 0; k < D3; k++) a += fs[k] * Wo1[k * D3 + t];
    t1[t] = fmaxf(a, 0.f);
    __syncthreads();
    float o = bo2[t];
    #pragma unroll 8
    for (int k = 0; k < D3; k++) o += t1[k] * Wo2[k * D3 + t];
    if (!g_valid[s]) o = 0.f;
    out[s * D3 + t] = o;
}

// =====================================================================================
extern "C" void kernel_launch(void* const* d_in, const int* in_sizes, int n_in,
                              void* d_out, int out_size)
{
    (void)in_sizes; (void)n_in; (void)out_size;
    const float* x   = (const float*)d_in[0];
    const int*   msk = (const int*)  d_in[1];
    const float* W1  = (const float*)d_in[2];
    const float* b1  = (const float*)d_in[3];
    const float* W2  = (const float*)d_in[4];
    const float* b2  = (const float*)d_in[5];
    const float* W3  = (const float*)d_in[6];
    const float* b3  = (const float*)d_in[7];
    const float* W4  = (const float*)d_in[8];
    const float* b4  = (const float*)d_in[9];
    const float* Wo1 = (const float*)d_in[10];
    const float* bo1 = (const float*)d_in[11];
    const float* Wo2 = (const float*)d_in[12];
    const float* bo2 = (const float*)d_in[13];
    float* out = (float*)d_out;

    const size_t smA = (size_t)(2048 + 8192 + 64 + 128 + 32 * 132 + 64 * 132 + 128 + 129) * 4;
    const size_t smB = (size_t)(64 * 132 + 64 * 128) * 4;
    const size_t smC = smB + (size_t)(128 + 128) * 4;

    cudaFuncSetAttribute(kA, cudaFuncAttributeMaxDynamicSharedMemorySize, (int)smA);
    cudaFuncSetAttribute(kB, cudaFuncAttributeMaxDynamicSharedMemorySize, (int)smB);
    cudaFuncSetAttribute(kC, cudaFuncAttributeMaxDynamicSharedMemorySize, (int)smC);

    kA<<<S_, 256, smA>>>(x, msk, W1, b1, W2, b2, W3, b3);
    kB<<<dim3(2, NPTS / 128), 256, smB>>>(W3);
    kC<<<dim3(2, NPTS / 128), 256, smC>>>(W4, b4, msk);
    kD<<<S_, 256>>>(Wo1, bo1, Wo2, bo2, out);
}

// round 2
// speedup vs baseline: 2.7955x; 2.7955x over previous
#include <cuda_runtime.h>
#include <cstdint>

#define S_  512      // B*T segments
#define P_  1024     // points per segment
#define C_  32       // input channels
#define D2  128      // pre hidden 2
#define D3  256      // between / out width
#define NPTS (S_ * P_)

// ---------------- global scratch (static __device__, no runtime alloc) ----------------
__device__ float g_h2[(size_t)NPTS * D2];   // masked h2 (256 MB)
__device__ float g_c[S_ * D3];              // per-segment pooled@W3_bot + b3
__device__ float g_feat[S_ * D3];           // segment max of h4
__device__ int   g_valid[S_];               // any-point-valid flag

__device__ __forceinline__ void atomicMaxF_nonneg(float* addr, float v) {
    atomicMax((int*)addr, __float_as_int(v));   // valid for non-negative floats
}

__device__ __forceinline__ uint32_t f2tf32(float x) {
    uint32_t r;
    asm("cvt.rna.tf32.f32 %0, %1;" : "=r"(r) : "f"(x));
    return r;
}

__device__ __forceinline__ void mma_tf32(float d[4], const uint32_t a[4], const uint32_t b[2]) {
    asm volatile(
        "mma.sync.aligned.m16n8k8.row.col.f32.tf32.tf32.f32 "
        "{%0,%1,%2,%3}, {%4,%5,%6,%7}, {%8,%9}, {%0,%1,%2,%3};\n"
        : "+f"(d[0]), "+f"(d[1]), "+f"(d[2]), "+f"(d[3])
        : "r"(a[0]), "r"(a[1]), "r"(a[2]), "r"(a[3]), "r"(b[0]), "r"(b[1]));
}

// =====================================================================================
// Kernel A (fp32, exact): per-segment fused pre-MLP.
//   x(1024x32) -> h1(64) -> h2(128), relu+mask, store h2 to scratch,
//   pooled = max_p h2, c = b3 + pooled @ W3[128:,:], valid flag, zero g_feat.
// =====================================================================================
__global__ void __launch_bounds__(256, 1)
kA(const float* __restrict__ x, const int* __restrict__ mask,
   const float* __restrict__ W1, const float* __restrict__ b1,
   const float* __restrict__ W2, const float* __restrict__ b2,
   const float* __restrict__ W3, const float* __restrict__ b3)
{
    extern __shared__ float sm[];
    float* W1s = sm;                   // 32*64
    float* W2s = W1s + 32 * 64;        // 64*128
    float* b1s = W2s + 64 * 128;       // 64
    float* b2s = b1s + 64;             // 128
    float* xs  = b2s + 128;            // [32][132]
    float* h1s = xs + 32 * 132;        // [64][132]
    float* pool = h1s + 64 * 132;      // 128
    int*   ms  = (int*)(pool + 128);   // 128
    int*   vf  = ms + 128;             // 1

    const int t = threadIdx.x;
    const int s = blockIdx.x;

    for (int i = t; i < 32 * 64;  i += 256) W1s[i] = W1[i];
    for (int i = t; i < 64 * 128; i += 256) W2s[i] = W2[i];
    if (t < 64)  b1s[t] = b1[t];
    if (t < 128) { b2s[t] = b2[t]; pool[t] = 0.f; }
    if (t == 0)  *vf = 0;
    g_feat[s * D3 + t] = 0.f;

    const int tx = t & 15, ty = t >> 4;
    const int r0 = ty * 8;
    const int c1 = tx * 4;
    const int c2 = tx * 8;

    float pmax[8];
    #pragma unroll
    for (int j = 0; j < 8; j++) pmax[j] = 0.f;

    for (int tile = 0; tile < 8; ++tile) {
        const int p0 = tile * 128;
        __syncthreads();
        {
            const int p = t >> 1;
            const int coff = (t & 1) * 16;
            const float* gx = x + (size_t)(s * P_ + p0 + p) * C_ + coff;
            #pragma unroll
            for (int q = 0; q < 4; q++) {
                float4 v = *(const float4*)(gx + 4 * q);
                xs[(coff + 4 * q + 0) * 132 + p] = v.x;
                xs[(coff + 4 * q + 1) * 132 + p] = v.y;
                xs[(coff + 4 * q + 2) * 132 + p] = v.z;
                xs[(coff + 4 * q + 3) * 132 + p] = v.w;
            }
        }
        if (t < 128) {
            int mv = (mask[s * P_ + p0 + t] != 0);
            ms[t] = mv;
            if (mv) atomicOr(vf, 1);
        }
        __syncthreads();
        {   // h1 = relu(x @ W1 + b1)
            float acc[8][4];
            #pragma unroll
            for (int i = 0; i < 8; i++)
                #pragma unroll
                for (int j = 0; j < 4; j++) acc[i][j] = b1s[c1 + j];
            #pragma unroll 8
            for (int k = 0; k < 32; k++) {
                float4 a0 = *(const float4*)&xs[k * 132 + r0];
                float4 a1 = *(const float4*)&xs[k * 132 + r0 + 4];
                float4 bv = *(const float4*)&W1s[k * 64 + c1];
                float a[8] = {a0.x, a0.y, a0.z, a0.w, a1.x, a1.y, a1.z, a1.w};
                float b[4] = {bv.x, bv.y, bv.z, bv.w};
                #pragma unroll
                for (int i = 0; i < 8; i++)
                    #pragma unroll
                    for (int j = 0; j < 4; j++) acc[i][j] += a[i] * b[j];
            }
            #pragma unroll
            for (int j = 0; j < 4; j++) {
                float4 v0, v1;
                v0.x = fmaxf(acc[0][j], 0.f); v0.y = fmaxf(acc[1][j], 0.f);
                v0.z = fmaxf(acc[2][j], 0.f); v0.w = fmaxf(acc[3][j], 0.f);
                v1.x = fmaxf(acc[4][j], 0.f); v1.y = fmaxf(acc[5][j], 0.f);
                v1.z = fmaxf(acc[6][j], 0.f); v1.w = fmaxf(acc[7][j], 0.f);
                *(float4*)&h1s[(c1 + j) * 132 + r0]     = v0;
                *(float4*)&h1s[(c1 + j) * 132 + r0 + 4] = v1;
            }
        }
        __syncthreads();
        {   // h2 = relu(h1 @ W2 + b2), mask, store, track max
            float acc[8][8];
            #pragma unroll
            for (int i = 0; i < 8; i++)
                #pragma unroll
                for (int j = 0; j < 8; j++) acc[i][j] = b2s[c2 + j];
            #pragma unroll 4
            for (int k = 0; k < 64; k++) {
                float4 a0 = *(const float4*)&h1s[k * 132 + r0];
                float4 a1 = *(const float4*)&h1s[k * 132 + r0 + 4];
                float4 b0v = *(const float4*)&W2s[k * 128 + c2];
                float4 b1v = *(const float4*)&W2s[k * 128 + c2 + 4];
                float a[8] = {a0.x, a0.y, a0.z, a0.w, a1.x, a1.y, a1.z, a1.w};
                float b[8] = {b0v.x, b0v.y, b0v.z, b0v.w, b1v.x, b1v.y, b1v.z, b1v.w};
                #pragma unroll
                for (int i = 0; i < 8; i++)
                    #pragma unroll
                    for (int j = 0; j < 8; j++) acc[i][j] += a[i] * b[j];
            }
            #pragma unroll
            for (int i = 0; i < 8; i++) {
                const int p = r0 + i;
                const int keep = ms[p];
                float v[8];
                #pragma unroll
                for (int j = 0; j < 8; j++) {
                    float z = fmaxf(acc[i][j], 0.f);
                    z = keep ? z : 0.f;
                    v[j] = z;
                    pmax[j] = fmaxf(pmax[j], z);
                }
                float* gp = g_h2 + (size_t)(s * P_ + p0 + p) * D2 + c2;
                *(float4*)gp       = make_float4(v[0], v[1], v[2], v[3]);
                *(float4*)(gp + 4) = make_float4(v[4], v[5], v[6], v[7]);
            }
        }
    }
    #pragma unroll
    for (int j = 0; j < 8; j++) atomicMaxF_nonneg(&pool[c2 + j], pmax[j]);
    __syncthreads();
    {   // c = b3 + pooled @ W3[128:, :]
        float acc = b3[t];
        #pragma unroll 4
        for (int k = 0; k < 128; k++)
            acc += pool[k] * W3[(size_t)(128 + k) * D3 + t];
        g_c[s * D3 + t] = acc;
    }
    if (t == 0) g_valid[s] = *vf;
}

// =====================================================================================
// Kernel BC (tf32 tensor): per 128-point tile,
//   for each 64-col chunk: h3chunk = relu(h2 @ W3_top[:,chunk] + c[chunk])   (stage1)
//                          acc    += h3chunk @ W4[chunk,:]                   (stage2)
//   epilogue: h4 = relu(acc + b4), mask rows, column-max -> atomicMax g_feat.
// 512 threads = 16 warps. Stage2 warp tile 32x64 (2x8 m16n8k8 atoms).
// Stage1 warp tile 32x16 (2x2 atoms). h3 never hits HBM.
// =====================================================================================
#define OFF_H2 0            // [128][132] tf32
#define OFF_W3 16896        // [128][72]  tf32 (64 cols used)
#define OFF_W4 26112        // [64][264]  tf32 (256 cols used)
#define OFF_H3 43008        // [128][68]  tf32
#define OFF_CV 51712        // 256 f32
#define OFF_B4 51968        // 256 f32
#define OFF_CM 52224        // 256 f32
#define OFF_MS 52480        // 128 int
#define SMW_BC 52608        // words -> 210432 bytes

__global__ void __launch_bounds__(512, 1)
kBC(const float* __restrict__ W3, const float* __restrict__ W4,
    const float* __restrict__ b4, const int* __restrict__ mask)
{
    extern __shared__ uint32_t smw[];
    uint32_t* h2s = smw + OFF_H2;
    uint32_t* w3s = smw + OFF_W3;
    uint32_t* w4s = smw + OFF_W4;
    uint32_t* h3s = smw + OFF_H3;
    float* cv   = (float*)(smw + OFF_CV);
    float* b4s  = (float*)(smw + OFF_B4);
    float* cmax = (float*)(smw + OFF_CM);
    int*   ms   = (int*)(smw + OFF_MS);

    const int t = threadIdx.x;
    const int lane = t & 31, wid = t >> 5;
    const int g = lane >> 2, tg = lane & 3;      // groupID / thread-in-group
    const int wm  = (wid & 3) * 32;              // warp m base (both stages)
    const int wn2 = (wid >> 2) * 64;             // stage2 warp n base
    const int wn1 = (wid >> 2) * 16;             // stage1 warp n base (chunk-local)
    const int m0 = blockIdx.x * 128;
    const int s  = m0 >> 10;

    if (t < 256) { cv[t] = g_c[s * D3 + t]; b4s[t] = b4[t]; cmax[t] = 0.f; }
    if (t < 128) ms[t] = (mask[m0 + t] != 0);

    // load h2 tile, round to tf32
    for (int i = t; i < 128 * 32; i += 512) {
        int row = i >> 5, c4 = (i & 31) * 4;
        float4 v = *(const float4*)(g_h2 + (size_t)(m0 + row) * D2 + c4);
        *(uint4*)(h2s + row * 132 + c4) =
            make_uint4(f2tf32(v.x), f2tf32(v.y), f2tf32(v.z), f2tf32(v.w));
    }

    float acc2[2][8][4];
    #pragma unroll
    for (int mi = 0; mi < 2; mi++)
        #pragma unroll
        for (int ni = 0; ni < 8; ni++)
            #pragma unroll
            for (int q = 0; q < 4; q++) acc2[mi][ni][q] = 0.f;

    for (int ch = 0; ch < 4; ++ch) {
        __syncthreads();    // prev chunk's stage2 done with w3s/w4s/h3s; h2s ready (ch=0)
        // W3_top chunk: rows 0..127 (k), cols ch*64..+64
        for (int i = t; i < 2048; i += 512) {
            int row = i >> 4, c4 = (i & 15) * 4;
            float4 v = *(const float4*)(W3 + (size_t)row * D3 + ch * 64 + c4);
            *(uint4*)(w3s + row * 72 + c4) =
                make_uint4(f2tf32(v.x), f2tf32(v.y), f2tf32(v.z), f2tf32(v.w));
        }
        // W4 chunk: rows ch*64..+64 (k), all 256 cols
        for (int i = t; i < 4096; i += 512) {
            int row = i >> 6, c4 = (i & 63) * 4;
            float4 v = *(const float4*)(W4 + (size_t)(ch * 64 + row) * D3 + c4);
            *(uint4*)(w4s + row * 264 + c4) =
                make_uint4(f2tf32(v.x), f2tf32(v.y), f2tf32(v.z), f2tf32(v.w));
        }
        __syncthreads();

        // ---- stage1: h3chunk = relu(h2 @ W3chunk + cv)  (M=128,N=64,K=128) ----
        float acc1[2][2][4];
        #pragma unroll
        for (int mi = 0; mi < 2; mi++)
            #pragma unroll
            for (int ni = 0; ni < 2; ni++)
                #pragma unroll
                for (int q = 0; q < 4; q++) acc1[mi][ni][q] = 0.f;

        #pragma unroll 4
        for (int k0 = 0; k0 < 128; k0 += 8) {
            uint32_t af[2][4];
            #pragma unroll
            for (int mi = 0; mi < 2; mi++) {
                int r = wm + mi * 16 + g;
                af[mi][0] = h2s[r * 132 + k0 + tg];
                af[mi][1] = h2s[(r + 8) * 132 + k0 + tg];
                af[mi][2] = h2s[r * 132 + k0 + tg + 4];
                af[mi][3] = h2s[(r + 8) * 132 + k0 + tg + 4];
            }
            uint32_t bf[2][2];
            #pragma unroll
            for (int ni = 0; ni < 2; ni++) {
                int c = wn1 + ni * 8 + g;
                bf[ni][0] = w3s[(k0 + tg) * 72 + c];
                bf[ni][1] = w3s[(k0 + tg + 4) * 72 + c];
            }
            #pragma unroll
            for (int mi = 0; mi < 2; mi++)
                #pragma unroll
                for (int ni = 0; ni < 2; ni++)
                    mma_tf32(acc1[mi][ni], af[mi], bf[ni]);
        }
        // stage1 epilogue: +c, relu, round to tf32, write h3s[m][k_local]
        #pragma unroll
        for (int mi = 0; mi < 2; mi++) {
            int r = wm + mi * 16 + g;
            #pragma unroll
            for (int ni = 0; ni < 2; ni++) {
                int c0 = wn1 + ni * 8 + 2 * tg;
                float cva = cv[ch * 64 + c0], cvb = cv[ch * 64 + c0 + 1];
                float v0 = fmaxf(acc1[mi][ni][0] + cva, 0.f);
                float v1 = fmaxf(acc1[mi][ni][1] + cvb, 0.f);
                float v2 = fmaxf(acc1[mi][ni][2] + cva, 0.f);
                float v3 = fmaxf(acc1[mi][ni][3] + cvb, 0.f);
                *(uint2*)(h3s + r * 68 + c0)       = make_uint2(f2tf32(v0), f2tf32(v1));
                *(uint2*)(h3s + (r + 8) * 68 + c0) = make_uint2(f2tf32(v2), f2tf32(v3));
            }
        }
        __syncthreads();

        // ---- stage2: acc2 += h3chunk @ W4chunk  (M=128,N=256,K=64) ----
        #pragma unroll
        for (int k0 = 0; k0 < 64; k0 += 8) {
            uint32_t af[2][4];
            #pragma unroll
            for (int mi = 0; mi < 2; mi++) {
                int r = wm + mi * 16 + g;
                af[mi][0] = h3s[r * 68 + k0 + tg];
                af[mi][1] = h3s[(r + 8) * 68 + k0 + tg];
                af[mi][2] = h3s[r * 68 + k0 + tg + 4];
                af[mi][3] = h3s[(r + 8) * 68 + k0 + tg + 4];
            }
            uint32_t bf[8][2];
            #pragma unroll
            for (int ni = 0; ni < 8; ni++) {
                int c = wn2 + ni * 8 + g;
                bf[ni][0] = w4s[(k0 + tg) * 264 + c];
                bf[ni][1] = w4s[(k0 + tg + 4) * 264 + c];
            }
            #pragma unroll
            for (int mi = 0; mi < 2; mi++)
                #pragma unroll
                for (int ni = 0; ni < 8; ni++)
                    mma_tf32(acc2[mi][ni], af[mi], bf[ni]);
        }
    }

    // ---- final epilogue: h4 = relu(acc2 + b4), mask rows, column max ----
    #pragma unroll
    for (int ni = 0; ni < 8; ni++) {
        int c0 = wn2 + ni * 8 + 2 * tg;
        float ba = b4s[c0], bb = b4s[c0 + 1];
        float mx0 = 0.f, mx1 = 0.f;
        #pragma unroll
        for (int mi = 0; mi < 2; mi++) {
            int r = wm + mi * 16 + g;
            int k0v = ms[r], k1v = ms[r + 8];
            float v0 = fmaxf(acc2[mi][ni][0] + ba, 0.f);
            float v1 = fmaxf(acc2[mi][ni][1] + bb, 0.f);
            float v2 = fmaxf(acc2[mi][ni][2] + ba, 0.f);
            float v3 = fmaxf(acc2[mi][ni][3] + bb, 0.f);
            if (k0v) { mx0 = fmaxf(mx0, v0); mx1 = fmaxf(mx1, v1); }
            if (k1v) { mx0 = fmaxf(mx0, v2); mx1 = fmaxf(mx1, v3); }
        }
        atomicMaxF_nonneg(&cmax[c0], mx0);
        atomicMaxF_nonneg(&cmax[c0 + 1], mx1);
    }
    __syncthreads();
    if (t < 256)
        atomicMax((int*)&g_feat[s * D3 + t], __float_as_int(cmax[t]));
}

// =====================================================================================
// Kernel D: per-segment out MLP (fp32, exact).
// =====================================================================================
__global__ void __launch_bounds__(256, 1)
kD(const float* __restrict__ Wo1, const float* __restrict__ bo1,
   const float* __restrict__ Wo2, const float* __restrict__ bo2,
   float* __restrict__ out)
{
    __shared__ float fs[D3], t1[D3];
    const int t = threadIdx.x, s = blockIdx.x;
    fs[t] = g_feat[s * D3 + t];
    __syncthreads();
    float a = bo1[t];
    #pragma unroll 8
    for (int k = 0; k < D3; k++) a += fs[k] * Wo1[k * D3 + t];
    t1[t] = fmaxf(a, 0.f);
    __syncthreads();
    float o = bo2[t];
    #pragma unroll 8
    for (int k = 0; k < D3; k++) o += t1[k] * Wo2[k * D3 + t];
    if (!g_valid[s]) o = 0.f;
    out[s * D3 + t] = o;
}

// =====================================================================================
extern "C" void kernel_launch(void* const* d_in, const int* in_sizes, int n_in,
                              void* d_out, int out_size)
{
    (void)in_sizes; (void)n_in; (void)out_size;
    const float* x   = (const float*)d_in[0];
    const int*   msk = (const int*)  d_in[1];
    const float* W1  = (const float*)d_in[2];
    const float* b1  = (const float*)d_in[3];
    const float* W2  = (const float*)d_in[4];
    const float* b2  = (const float*)d_in[5];
    const float* W3  = (const float*)d_in[6];
    const float* b3  = (const float*)d_in[7];
    const float* W4  = (const float*)d_in[8];
    const float* b4  = (const float*)d_in[9];
    const float* Wo1 = (const float*)d_in[10];
    const float* bo1 = (const float*)d_in[11];
    const float* Wo2 = (const float*)d_in[12];
    const float* bo2 = (const float*)d_in[13];
    float* out = (float*)d_out;

    const size_t smA  = (size_t)(2048 + 8192 + 64 + 128 + 32 * 132 + 64 * 132 + 128 + 129) * 4;
    const size_t smBC = (size_t)SMW_BC * 4;   // 210432 bytes

    cudaFuncSetAttribute(kA,  cudaFuncAttributeMaxDynamicSharedMemorySize, (int)smA);
    cudaFuncSetAttribute(kBC, cudaFuncAttributeMaxDynamicSharedMemorySize, (int)smBC);

    kA<<<S_, 256, smA>>>(x, msk, W1, b1, W2, b2, W3, b3);
    kBC<<<NPTS / 128, 512, smBC>>>(W3, W4, b4, msk);
    kD<<<S_, 256>>>(Wo1, bo1, Wo2, bo2, out);
}

// round 3
// speedup vs baseline: 3.6318x; 1.2992x over previous
#include <cuda_runtime.h>
#include <cstdint>

#define S_  512      // B*T segments
#define P_  1024     // points per segment
#define D3  256
#define NPTS (S_ * P_)

// ---------------- global scratch ----------------
__device__ uint32_t g_h2[(size_t)NPTS * 128];  // masked h2 as tf32 bits (256 MB)
__device__ float g_pool[S_ * 128];             // per-segment max of h2
__device__ float g_c[S_ * D3];                 // b3 + pooled @ W3_bot
__device__ float g_feat[S_ * D3];              // segment max of h4
__device__ int   g_valid[S_];

__device__ __forceinline__ void atomicMaxF_nonneg(float* addr, float v) {
    atomicMax((int*)addr, __float_as_int(v));   // valid for non-negative floats
}
__device__ __forceinline__ uint32_t f2tf32(float x) {
    uint32_t r; asm("cvt.rna.tf32.f32 %0, %1;" : "=r"(r) : "f"(x)); return r;
}
__device__ __forceinline__ void mma_tf32(float d[4], const uint32_t a[4], const uint32_t b[2]) {
    asm volatile(
        "mma.sync.aligned.m16n8k8.row.col.f32.tf32.tf32.f32 "
        "{%0,%1,%2,%3}, {%4,%5,%6,%7}, {%8,%9}, {%0,%1,%2,%3};\n"
        : "+f"(d[0]), "+f"(d[1]), "+f"(d[2]), "+f"(d[3])
        : "r"(a[0]), "r"(a[1]), "r"(a[2]), "r"(a[3]), "r"(b[0]), "r"(b[1]));
}

// ============================= kZ: zero the accumulators =============================
__global__ void kZ() {
    int i = blockIdx.x * 256 + threadIdx.x;         // grid 512 -> i < 131072
    g_feat[i] = 0.f;
    if (i < S_ * 128) g_pool[i] = 0.f;
    if (i < S_) g_valid[i] = 0;
}

// =====================================================================================
// Kernel A (tf32 MMA): 128 points per CTA, grid 4096, 256 threads, 2 CTAs/SM.
//   x -> h1(64) -> h2(128) relu+mask, store tf32 bits to g_h2,
//   col-max -> atomicMax g_pool, valid -> atomicOr g_valid.
// smem word offsets:
#define A_XS  0        // [128][36]
#define A_W1  4608     // [32][72]
#define A_H1  6912     // [128][68]
#define A_W2  15616    // [64][136]
#define A_B1  24320    // 64
#define A_B2  24384    // 128
#define A_PL  24512    // 128
#define A_MS  24640    // 128 (int)
#define A_VF  24768    // 1
#define A_SMW 24769
// =====================================================================================
__global__ void __launch_bounds__(256, 2)
kA(const float* __restrict__ x, const int* __restrict__ mask,
   const float* __restrict__ W1, const float* __restrict__ b1,
   const float* __restrict__ W2, const float* __restrict__ b2)
{
    extern __shared__ uint32_t smw[];
    uint32_t* xs  = smw + A_XS;
    uint32_t* w1s = smw + A_W1;
    uint32_t* h1s = smw + A_H1;
    uint32_t* w2s = smw + A_W2;
    float* b1s = (float*)(smw + A_B1);
    float* b2s = (float*)(smw + A_B2);
    float* pl  = (float*)(smw + A_PL);
    int*   ms  = (int*)(smw + A_MS);
    int*   vf  = (int*)(smw + A_VF);

    const int t = threadIdx.x;
    const int lane = t & 31, wid = t >> 5;
    const int g = lane >> 2, tg = lane & 3;
    const int m0 = blockIdx.x * 128;
    const int s  = m0 >> 10;

    // ---- loads ----
    {
        const int r = t >> 1, c16 = (t & 1) * 16;
        const float* gx = x + (size_t)(m0 + r) * 32 + c16;
        #pragma unroll
        for (int q = 0; q < 4; q++) {
            float4 v = *(const float4*)(gx + 4 * q);
            *(uint4*)(xs + r * 36 + c16 + 4 * q) =
                make_uint4(f2tf32(v.x), f2tf32(v.y), f2tf32(v.z), f2tf32(v.w));
        }
    }
    for (int i = t; i < 2048; i += 256) w1s[(i >> 6) * 72 + (i & 63)] = f2tf32(W1[i]);
    for (int i = t; i < 8192; i += 256) w2s[(i >> 7) * 136 + (i & 127)] = f2tf32(W2[i]);
    if (t < 64)  b1s[t] = b1[t];
    if (t < 128) { b2s[t] = b2[t]; pl[t] = 0.f; }
    if (t == 0)  *vf = 0;
    if (t < 128) {
        int mv = (mask[m0 + t] != 0);
        ms[t] = mv;
        if (mv) atomicOr(vf, 1);
    }
    __syncthreads();

    // ---- h1 = relu(x@W1+b1): M128,N64,K32; warp tile 16x64 ----
    {
        const int wm1 = wid * 16;
        float acc[8][4];
        #pragma unroll
        for (int ni = 0; ni < 8; ni++) {
            float ba = b1s[ni * 8 + 2 * tg], bb = b1s[ni * 8 + 2 * tg + 1];
            acc[ni][0] = ba; acc[ni][1] = bb; acc[ni][2] = ba; acc[ni][3] = bb;
        }
        #pragma unroll
        for (int k0 = 0; k0 < 32; k0 += 8) {
            uint32_t af[4];
            const int r = wm1 + g;
            af[0] = xs[r * 36 + k0 + tg];
            af[1] = xs[(r + 8) * 36 + k0 + tg];
            af[2] = xs[r * 36 + k0 + tg + 4];
            af[3] = xs[(r + 8) * 36 + k0 + tg + 4];
            uint32_t bf[8][2];
            #pragma unroll
            for (int ni = 0; ni < 8; ni++) {
                bf[ni][0] = w1s[(k0 + tg) * 72 + ni * 8 + g];
                bf[ni][1] = w1s[(k0 + tg + 4) * 72 + ni * 8 + g];
            }
            #pragma unroll
            for (int ni = 0; ni < 8; ni++) mma_tf32(acc[ni], af, bf[ni]);
        }
        const int r = wm1 + g;
        #pragma unroll
        for (int ni = 0; ni < 8; ni++) {
            int c0 = ni * 8 + 2 * tg;
            *(uint2*)(h1s + r * 68 + c0) = make_uint2(
                f2tf32(fmaxf(acc[ni][0], 0.f)), f2tf32(fmaxf(acc[ni][1], 0.f)));
            *(uint2*)(h1s + (r + 8) * 68 + c0) = make_uint2(
                f2tf32(fmaxf(acc[ni][2], 0.f)), f2tf32(fmaxf(acc[ni][3], 0.f)));
        }
    }
    __syncthreads();

    // ---- h2 = relu(h1@W2+b2) mask store: M128,N128,K64; warp tile 32x64 ----
    {
        const int wm = (wid & 3) * 32, wn = (wid >> 2) * 64;
        float acc[2][8][4];
        #pragma unroll
        for (int mi = 0; mi < 2; mi++)
            #pragma unroll
            for (int ni = 0; ni < 8; ni++) {
                float ba = b2s[wn + ni * 8 + 2 * tg], bb = b2s[wn + ni * 8 + 2 * tg + 1];
                acc[mi][ni][0] = ba; acc[mi][ni][1] = bb;
                acc[mi][ni][2] = ba; acc[mi][ni][3] = bb;
            }
        #pragma unroll
        for (int k0 = 0; k0 < 64; k0 += 8) {
            uint32_t af[2][4];
            #pragma unroll
            for (int mi = 0; mi < 2; mi++) {
                const int r = wm + mi * 16 + g;
                af[mi][0] = h1s[r * 68 + k0 + tg];
                af[mi][1] = h1s[(r + 8) * 68 + k0 + tg];
                af[mi][2] = h1s[r * 68 + k0 + tg + 4];
                af[mi][3] = h1s[(r + 8) * 68 + k0 + tg + 4];
            }
            uint32_t bf[8][2];
            #pragma unroll
            for (int ni = 0; ni < 8; ni++) {
                bf[ni][0] = w2s[(k0 + tg) * 136 + wn + ni * 8 + g];
                bf[ni][1] = w2s[(k0 + tg + 4) * 136 + wn + ni * 8 + g];
            }
            #pragma unroll
            for (int mi = 0; mi < 2; mi++)
                #pragma unroll
                for (int ni = 0; ni < 8; ni++) mma_tf32(acc[mi][ni], af[mi], bf[ni]);
        }
        float pmax[8][2];
        #pragma unroll
        for (int ni = 0; ni < 8; ni++) { pmax[ni][0] = 0.f; pmax[ni][1] = 0.f; }
        #pragma unroll
        for (int mi = 0; mi < 2; mi++) {
            const int r = wm + mi * 16 + g;
            const int k0v = ms[r], k1v = ms[r + 8];
            #pragma unroll
            for (int ni = 0; ni < 8; ni++) {
                int c0 = wn + ni * 8 + 2 * tg;
                float v0 = k0v ? fmaxf(acc[mi][ni][0], 0.f) : 0.f;
                float v1 = k0v ? fmaxf(acc[mi][ni][1], 0.f) : 0.f;
                float v2 = k1v ? fmaxf(acc[mi][ni][2], 0.f) : 0.f;
                float v3 = k1v ? fmaxf(acc[mi][ni][3], 0.f) : 0.f;
                pmax[ni][0] = fmaxf(pmax[ni][0], fmaxf(v0, v2));
                pmax[ni][1] = fmaxf(pmax[ni][1], fmaxf(v1, v3));
                *(uint2*)(g_h2 + (size_t)(m0 + r) * 128 + c0) =
                    make_uint2(f2tf32(v0), f2tf32(v1));
                *(uint2*)(g_h2 + (size_t)(m0 + r + 8) * 128 + c0) =
                    make_uint2(f2tf32(v2), f2tf32(v3));
            }
        }
        #pragma unroll
        for (int ni = 0; ni < 8; ni++) {
            atomicMaxF_nonneg(&pl[wn + ni * 8 + 2 * tg], pmax[ni][0]);
            atomicMaxF_nonneg(&pl[wn + ni * 8 + 2 * tg + 1], pmax[ni][1]);
        }
    }
    __syncthreads();
    if (t < 128) atomicMaxF_nonneg(&g_pool[s * 128 + t], pl[t]);
    if (t == 0 && *vf) atomicOr(&g_valid[s], 1);
}

// ============================= kA2: c = b3 + pool @ W3_bot =============================
__global__ void __launch_bounds__(256, 4)
kA2(const float* __restrict__ W3, const float* __restrict__ b3)
{
    __shared__ float ps[128];
    const int t = threadIdx.x, s = blockIdx.x;
    if (t < 128) ps[t] = g_pool[s * 128 + t];
    __syncthreads();
    float acc = b3[t];
    #pragma unroll 8
    for (int k = 0; k < 128; k++)
        acc += ps[k] * W3[(size_t)(128 + k) * D3 + t];
    g_c[s * D3 + t] = acc;
}

// =====================================================================================
// kBC: phase1 full-K GEMM h3 = relu(h2@W3_top + c)  (M128,N256,K128) in smem,
//      phase2 acc = h3@W4 with k=32 double-buffered chunks (reg-prefetched),
//      epilogue h4 = relu(acc [b4 folded in init]), mask rows, colmax -> g_feat.
// smem word offsets:
#define BC_H2  0        // [128][132] h2 tile; later W4 dbl-buf [32][264] x2 (A1 @ +8448)
#define BC_W3  16896    // [128][264] W3 full; later h3 [128][260]
#define BC_CV  50688    // 256
#define BC_B4  50944    // 256
#define BC_CM  51200    // 256
#define BC_MS  51456    // 128 (int)
#define BC_SMW 51584
// =====================================================================================
__global__ void __launch_bounds__(512, 1)
kBC(const float* __restrict__ W3, const float* __restrict__ W4,
    const float* __restrict__ b4, const int* __restrict__ mask)
{
    extern __shared__ uint32_t smw[];
    uint32_t* h2s = smw + BC_H2;
    uint32_t* w3s = smw + BC_W3;
    uint32_t* h3s = smw + BC_W3;            // overlays W3 after phase1
    float* cv   = (float*)(smw + BC_CV);
    float* b4s  = (float*)(smw + BC_B4);
    float* cmax = (float*)(smw + BC_CM);
    int*   ms   = (int*)(smw + BC_MS);

    const int t = threadIdx.x;
    const int lane = t & 31, wid = t >> 5;
    const int g = lane >> 2, tg = lane & 3;
    const int wm = (wid & 3) * 32;
    const int wn = (wid >> 2) * 64;
    const int m0 = blockIdx.x * 128;
    const int s  = m0 >> 10;

    if (t < 256) { cv[t] = g_c[s * D3 + t]; b4s[t] = b4[t]; cmax[t] = 0.f; }
    if (t < 128) ms[t] = (mask[m0 + t] != 0);

    for (int i = t; i < 4096; i += 512) {            // h2 tile: tf32 bits, direct copy
        int row = i >> 5, c4 = (i & 31) * 4;
        *(uint4*)(h2s + row * 132 + c4) =
            *(const uint4*)(g_h2 + (size_t)(m0 + row) * 128 + c4);
    }
    for (int i = t; i < 8192; i += 512) {            // W3 top full (128x256), cvt
        int row = i >> 6, c4 = (i & 63) * 4;
        float4 v = *(const float4*)(W3 + (size_t)row * D3 + c4);
        *(uint4*)(w3s + row * 264 + c4) =
            make_uint4(f2tf32(v.x), f2tf32(v.y), f2tf32(v.z), f2tf32(v.w));
    }
    __syncthreads();

    // ---- phase1 ----
    float acc[2][8][4];
    #pragma unroll
    for (int mi = 0; mi < 2; mi++)
        #pragma unroll
        for (int ni = 0; ni < 8; ni++) {
            float ca = cv[wn + ni * 8 + 2 * tg], cb = cv[wn + ni * 8 + 2 * tg + 1];
            acc[mi][ni][0] = ca; acc[mi][ni][1] = cb;
            acc[mi][ni][2] = ca; acc[mi][ni][3] = cb;
        }
    #pragma unroll 4
    for (int k0 = 0; k0 < 128; k0 += 8) {
        uint32_t af[2][4];
        #pragma unroll
        for (int mi = 0; mi < 2; mi++) {
            const int r = wm + mi * 16 + g;
            af[mi][0] = h2s[r * 132 + k0 + tg];
            af[mi][1] = h2s[(r + 8) * 132 + k0 + tg];
            af[mi][2] = h2s[r * 132 + k0 + tg + 4];
            af[mi][3] = h2s[(r + 8) * 132 + k0 + tg + 4];
        }
        uint32_t bf[8][2];
        #pragma unroll
        for (int ni = 0; ni < 8; ni++) {
            bf[ni][0] = w3s[(k0 + tg) * 264 + wn + ni * 8 + g];
            bf[ni][1] = w3s[(k0 + tg + 4) * 264 + wn + ni * 8 + g];
        }
        #pragma unroll
        for (int mi = 0; mi < 2; mi++)
            #pragma unroll
            for (int ni = 0; ni < 8; ni++) mma_tf32(acc[mi][ni], af[mi], bf[ni]);
    }
    __syncthreads();   // everyone done reading h2s/w3s

    // ---- epilogue1: h3 (tf32) overwrites W3 region; also load W4 chunk0 into bufA ----
    #pragma unroll
    for (int mi = 0; mi < 2; mi++) {
        const int r = wm + mi * 16 + g;
        #pragma unroll
        for (int ni = 0; ni < 8; ni++) {
            int c0 = wn + ni * 8 + 2 * tg;
            *(uint2*)(h3s + r * 260 + c0) = make_uint2(
                f2tf32(fmaxf(acc[mi][ni][0], 0.f)), f2tf32(fmaxf(acc[mi][ni][1], 0.f)));
            *(uint2*)(h3s + (r + 8) * 260 + c0) = make_uint2(
                f2tf32(fmaxf(acc[mi][ni][2], 0.f)), f2tf32(fmaxf(acc[mi][ni][3], 0.f)));
        }
    }
    #pragma unroll
    for (int j = 0; j < 4; j++) {                    // W4 rows 0..31 -> buffer A0
        int i = t + j * 512;
        int row = i >> 6, c4 = (i & 63) * 4;
        float4 v = *(const float4*)(W4 + (size_t)row * D3 + c4);
        *(uint4*)(h2s + row * 264 + c4) =
            make_uint4(f2tf32(v.x), f2tf32(v.y), f2tf32(v.z), f2tf32(v.w));
    }
    __syncthreads();

    // ---- phase2: 8 chunks of k=32, double-buffered W4, 1 sync per chunk ----
    float acc2[2][8][4];
    #pragma unroll
    for (int mi = 0; mi < 2; mi++)
        #pragma unroll
        for (int ni = 0; ni < 8; ni++) {
            float ba = b4s[wn + ni * 8 + 2 * tg], bb = b4s[wn + ni * 8 + 2 * tg + 1];
            acc2[mi][ni][0] = ba; acc2[mi][ni][1] = bb;
            acc2[mi][ni][2] = ba; acc2[mi][ni][3] = bb;
        }
    for (int ch = 0; ch < 8; ++ch) {
        uint32_t* wbuf = h2s + (ch & 1) * 8448;
        float4 pre[4];
        if (ch < 7) {
            #pragma unroll
            for (int j = 0; j < 4; j++) {
                int i = t + j * 512;
                int row = i >> 6, c4 = (i & 63) * 4;
                pre[j] = *(const float4*)(W4 + (size_t)((ch + 1) * 32 + row) * D3 + c4);
            }
        }
        #pragma unroll
        for (int k0 = 0; k0 < 32; k0 += 8) {
            uint32_t af[2][4];
            #pragma unroll
            for (int mi = 0; mi < 2; mi++) {
                const int r = wm + mi * 16 + g;
                af[mi][0] = h3s[r * 260 + ch * 32 + k0 + tg];
                af[mi][1] = h3s[(r + 8) * 260 + ch * 32 + k0 + tg];
                af[mi][2] = h3s[r * 260 + ch * 32 + k0 + tg + 4];
                af[mi][3] = h3s[(r + 8) * 260 + ch * 32 + k0 + tg + 4];
            }
            uint32_t bf[8][2];
            #pragma unroll
            for (int ni = 0; ni < 8; ni++) {
                bf[ni][0] = wbuf[(k0 + tg) * 264 + wn + ni * 8 + g];
                bf[ni][1] = wbuf[(k0 + tg + 4) * 264 + wn + ni * 8 + g];
            }
            #pragma unroll
            for (int mi = 0; mi < 2; mi++)
                #pragma unroll
                for (int ni = 0; ni < 8; ni++) mma_tf32(acc2[mi][ni], af[mi], bf[ni]);
        }
        if (ch < 7) {
            uint32_t* dbuf = h2s + ((ch + 1) & 1) * 8448;
            #pragma unroll
            for (int j = 0; j < 4; j++) {
                int i = t + j * 512;
                int row = i >> 6, c4 = (i & 63) * 4;
                *(uint4*)(dbuf + row * 264 + c4) = make_uint4(
                    f2tf32(pre[j].x), f2tf32(pre[j].y), f2tf32(pre[j].z), f2tf32(pre[j].w));
            }
        }
        __syncthreads();
    }

    // ---- final epilogue ----
    #pragma unroll
    for (int ni = 0; ni < 8; ni++) {
        int c0 = wn + ni * 8 + 2 * tg;
        float mx0 = 0.f, mx1 = 0.f;
        #pragma unroll
        for (int mi = 0; mi < 2; mi++) {
            const int r = wm + mi * 16 + g;
            const int k0v = ms[r], k1v = ms[r + 8];
            float v0 = fmaxf(acc2[mi][ni][0], 0.f);
            float v1 = fmaxf(acc2[mi][ni][1], 0.f);
            float v2 = fmaxf(acc2[mi][ni][2], 0.f);
            float v3 = fmaxf(acc2[mi][ni][3], 0.f);
            if (k0v) { mx0 = fmaxf(mx0, v0); mx1 = fmaxf(mx1, v1); }
            if (k1v) { mx0 = fmaxf(mx0, v2); mx1 = fmaxf(mx1, v3); }
        }
        atomicMaxF_nonneg(&cmax[c0], mx0);
        atomicMaxF_nonneg(&cmax[c0 + 1], mx1);
    }
    __syncthreads();
    if (t < 256)
        atomicMax((int*)&g_feat[s * D3 + t], __float_as_int(cmax[t]));
}

// ============================= kD: per-segment out MLP =============================
__global__ void __launch_bounds__(256, 1)
kD(const float* __restrict__ Wo1, const float* __restrict__ bo1,
   const float* __restrict__ Wo2, const float* __restrict__ bo2,
   float* __restrict__ out)
{
    __shared__ float fs[D3], t1[D3];
    const int t = threadIdx.x, s = blockIdx.x;
    fs[t] = g_feat[s * D3 + t];
    __syncthreads();
    float a = bo1[t];
    #pragma unroll 8
    for (int k = 0; k < D3; k++) a += fs[k] * Wo1[k * D3 + t];
    t1[t] = fmaxf(a, 0.f);
    __syncthreads();
    float o = bo2[t];
    #pragma unroll 8
    for (int k = 0; k < D3; k++) o += t1[k] * Wo2[k * D3 + t];
    if (!g_valid[s]) o = 0.f;
    out[s * D3 + t] = o;
}

// =====================================================================================
extern "C" void kernel_launch(void* const* d_in, const int* in_sizes, int n_in,
                              void* d_out, int out_size)
{
    (void)in_sizes; (void)n_in; (void)out_size;
    const float* x   = (const float*)d_in[0];
    const int*   msk = (const int*)  d_in[1];
    const float* W1  = (const float*)d_in[2];
    const float* b1  = (const float*)d_in[3];
    const float* W2  = (const float*)d_in[4];
    const float* b2  = (const float*)d_in[5];
    const float* W3  = (const float*)d_in[6];
    const float* b3  = (const float*)d_in[7];
    const float* W4  = (const float*)d_in[8];
    const float* b4  = (const float*)d_in[9];
    const float* Wo1 = (const float*)d_in[10];
    const float* bo1 = (const float*)d_in[11];
    const float* Wo2 = (const float*)d_in[12];
    const float* bo2 = (const float*)d_in[13];
    float* out = (float*)d_out;

    const size_t smA  = (size_t)A_SMW * 4;    //  99 KB
    const size_t smBC = (size_t)BC_SMW * 4;   // 206 KB

    cudaFuncSetAttribute(kA,  cudaFuncAttributeMaxDynamicSharedMemorySize, (int)smA);
    cudaFuncSetAttribute(kBC, cudaFuncAttributeMaxDynamicSharedMemorySize, (int)smBC);

    kZ <<<S_, 256>>>();
    kA <<<NPTS / 128, 256, smA>>>(x, msk, W1, b1, W2, b2);
    kA2<<<S_, 256>>>(W3, b3);
    kBC<<<NPTS / 128, 512, smBC>>>(W3, W4, b4, msk);
    kD <<<S_, 256>>>(Wo1, bo1, Wo2, bo2, out);
}

// round 6
// speedup vs baseline: 4.2074x; 1.1585x over previous
#include <cuda_runtime.h>
#include <cstdint>

#define S_  512      // B*T segments
#define P_  1024     // points per segment
#define D3  256
#define NPTS (S_ * P_)

// ---------------- global scratch ----------------
__device__ uint32_t g_h2[(size_t)NPTS * 128];  // masked h2 as tf32 bits (256 MB)
__device__ uint32_t g_w3t[256 * 128];          // W3 top, tf32, [n][k]
__device__ uint32_t g_w4t[256 * 256];          // W4, tf32, [n][k]
__device__ float g_pool[S_ * 128];
__device__ float g_c[S_ * D3];
__device__ float g_feat[S_ * D3];
__device__ int   g_valid[S_];

__device__ __forceinline__ void atomicMaxF_nonneg(float* addr, float v) {
    atomicMax((int*)addr, __float_as_int(v));   // valid for non-negative floats
}
__device__ __forceinline__ uint32_t f2tf32(float x) {
    uint32_t r; asm("cvt.rna.tf32.f32 %0, %1;" : "=r"(r) : "f"(x)); return r;
}
__device__ __forceinline__ void mma_tf32(float d[4], const uint32_t a[4], const uint32_t b[2]) {
    asm volatile(
        "mma.sync.aligned.m16n8k8.row.col.f32.tf32.tf32.f32 "
        "{%0,%1,%2,%3}, {%4,%5,%6,%7}, {%8,%9}, {%0,%1,%2,%3};\n"
        : "+f"(d[0]), "+f"(d[1]), "+f"(d[2]), "+f"(d[3])
        : "r"(a[0]), "r"(a[1]), "r"(a[2]), "r"(a[3]), "r"(b[0]), "r"(b[1]));
}
__device__ __forceinline__ void ldsm4(uint32_t d[4], uint32_t addr) {
    asm volatile("ldmatrix.sync.aligned.m8n8.x4.shared.b16 {%0,%1,%2,%3}, [%4];"
                 : "=r"(d[0]), "=r"(d[1]), "=r"(d[2]), "=r"(d[3]) : "r"(addr));
}
__device__ __forceinline__ void cp_async16(uint32_t saddr, const void* gaddr) {
    asm volatile("cp.async.cg.shared.global [%0], [%1], 16;"
                 :: "r"(saddr), "l"(gaddr) : "memory");
}
__device__ __forceinline__ void cp_commit() {
    asm volatile("cp.async.commit_group;" ::: "memory");
}

// ============================= kZ: zero the accumulators =============================
__global__ void kZ() {
    int i = blockIdx.x * 256 + threadIdx.x;     // grid 512 -> i < 131072
    g_feat[i] = 0.f;
    if (i < S_ * 128) g_pool[i] = 0.f;
    if (i < S_) g_valid[i] = 0;
}

// =========== kP: pack W (K x N f32 row-major) -> dst [n][k] tf32 words ==============
__global__ void kP(const float* __restrict__ W, uint32_t* __restrict__ dst, int K, int N) {
    int i = blockIdx.x * 256 + threadIdx.x;
    if (i >= K * N) return;
    int n = i % N, k = i / N;
    dst[n * K + k] = f2tf32(W[k * N + n]);
}

// =====================================================================================
// Kernel A (tf32 MMA, same as passing R3): 128 points/CTA, grid 4096, 256 thr.
#define A_XS  0        // [128][36]
#define A_W1  4608     // [32][72]
#define A_H1  6912     // [128][68]
#define A_W2  15616    // [64][136]
#define A_B1  24320    // 64
#define A_B2  24384    // 128
#define A_PL  24512    // 128
#define A_MS  24640    // 128 (int)
#define A_VF  24768    // 1
#define A_SMW 24769
// =====================================================================================
__global__ void __launch_bounds__(256, 2)
kA(const float* __restrict__ x, const int* __restrict__ mask,
   const float* __restrict__ W1, const float* __restrict__ b1,
   const float* __restrict__ W2, const float* __restrict__ b2)
{
    extern __shared__ uint32_t smw[];
    uint32_t* xs  = smw + A_XS;
    uint32_t* w1s = smw + A_W1;
    uint32_t* h1s = smw + A_H1;
    uint32_t* w2s = smw + A_W2;
    float* b1s = (float*)(smw + A_B1);
    float* b2s = (float*)(smw + A_B2);
    float* pl  = (float*)(smw + A_PL);
    int*   ms  = (int*)(smw + A_MS);
    int*   vf  = (int*)(smw + A_VF);

    const int t = threadIdx.x;
    const int lane = t & 31, wid = t >> 5;
    const int g = lane >> 2, tg = lane & 3;
    const int m0 = blockIdx.x * 128;
    const int s  = m0 >> 10;

    {
        const int r = t >> 1, c16 = (t & 1) * 16;
        const float* gx = x + (size_t)(m0 + r) * 32 + c16;
        #pragma unroll
        for (int q = 0; q < 4; q++) {
            float4 v = *(const float4*)(gx + 4 * q);
            *(uint4*)(xs + r * 36 + c16 + 4 * q) =
                make_uint4(f2tf32(v.x), f2tf32(v.y), f2tf32(v.z), f2tf32(v.w));
        }
    }
    for (int i = t; i < 2048; i += 256) w1s[(i >> 6) * 72 + (i & 63)] = f2tf32(W1[i]);
    for (int i = t; i < 8192; i += 256) w2s[(i >> 7) * 136 + (i & 127)] = f2tf32(W2[i]);
    if (t < 64)  b1s[t] = b1[t];
    if (t < 128) { b2s[t] = b2[t]; pl[t] = 0.f; }
    if (t == 0)  *vf = 0;
    if (t < 128) {
        int mv = (mask[m0 + t] != 0);
        ms[t] = mv;
        if (mv) atomicOr(vf, 1);
    }
    __syncthreads();

    // h1 = relu(x@W1+b1): M128,N64,K32; warp tile 16x64
    {
        const int wm1 = wid * 16;
        float acc[8][4];
        #pragma unroll
        for (int ni = 0; ni < 8; ni++) {
            float ba = b1s[ni * 8 + 2 * tg], bb = b1s[ni * 8 + 2 * tg + 1];
            acc[ni][0] = ba; acc[ni][1] = bb; acc[ni][2] = ba; acc[ni][3] = bb;
        }
        #pragma unroll
        for (int k0 = 0; k0 < 32; k0 += 8) {
            uint32_t af[4];
            const int r = wm1 + g;
            af[0] = xs[r * 36 + k0 + tg];
            af[1] = xs[(r + 8) * 36 + k0 + tg];
            af[2] = xs[r * 36 + k0 + tg + 4];
            af[3] = xs[(r + 8) * 36 + k0 + tg + 4];
            uint32_t bf[8][2];
            #pragma unroll
            for (int ni = 0; ni < 8; ni++) {
                bf[ni][0] = w1s[(k0 + tg) * 72 + ni * 8 + g];
                bf[ni][1] = w1s[(k0 + tg + 4) * 72 + ni * 8 + g];
            }
            #pragma unroll
            for (int ni = 0; ni < 8; ni++) mma_tf32(acc[ni], af, bf[ni]);
        }
        const int r = wm1 + g;
        #pragma unroll
        for (int ni = 0; ni < 8; ni++) {
            int c0 = ni * 8 + 2 * tg;
            *(uint2*)(h1s + r * 68 + c0) = make_uint2(
                f2tf32(fmaxf(acc[ni][0], 0.f)), f2tf32(fmaxf(acc[ni][1], 0.f)));
            *(uint2*)(h1s + (r + 8) * 68 + c0) = make_uint2(
                f2tf32(fmaxf(acc[ni][2], 0.f)), f2tf32(fmaxf(acc[ni][3], 0.f)));
        }
    }
    __syncthreads();

    // h2 = relu(h1@W2+b2) mask store: M128,N128,K64; warp tile 32x64
    {
        const int wm = (wid & 3) * 32, wn = (wid >> 2) * 64;
        float acc[2][8][4];
        #pragma unroll
        for (int mi = 0; mi < 2; mi++)
            #pragma unroll
            for (int ni = 0; ni < 8; ni++) {
                float ba = b2s[wn + ni * 8 + 2 * tg], bb = b2s[wn + ni * 8 + 2 * tg + 1];
                acc[mi][ni][0] = ba; acc[mi][ni][1] = bb;
                acc[mi][ni][2] = ba; acc[mi][ni][3] = bb;
            }
        #pragma unroll
        for (int k0 = 0; k0 < 64; k0 += 8) {
            uint32_t af[2][4];
            #pragma unroll
            for (int mi = 0; mi < 2; mi++) {
                const int r = wm + mi * 16 + g;
                af[mi][0] = h1s[r * 68 + k0 + tg];
                af[mi][1] = h1s[(r + 8) * 68 + k0 + tg];
                af[mi][2] = h1s[r * 68 + k0 + tg + 4];
                af[mi][3] = h1s[(r + 8) * 68 + k0 + tg + 4];
            }
            uint32_t bf[8][2];
            #pragma unroll
            for (int ni = 0; ni < 8; ni++) {
                bf[ni][0] = w2s[(k0 + tg) * 136 + wn + ni * 8 + g];
                bf[ni][1] = w2s[(k0 + tg + 4) * 136 + wn + ni * 8 + g];
            }
            #pragma unroll
            for (int mi = 0; mi < 2; mi++)
                #pragma unroll
                for (int ni = 0; ni < 8; ni++) mma_tf32(acc[mi][ni], af[mi], bf[ni]);
        }
        float pmax[8][2];
        #pragma unroll
        for (int ni = 0; ni < 8; ni++) { pmax[ni][0] = 0.f; pmax[ni][1] = 0.f; }
        #pragma unroll
        for (int mi = 0; mi < 2; mi++) {
            const int r = wm + mi * 16 + g;
            const int k0v = ms[r], k1v = ms[r + 8];
            #pragma unroll
            for (int ni = 0; ni < 8; ni++) {
                int c0 = wn + ni * 8 + 2 * tg;
                float v0 = k0v ? fmaxf(acc[mi][ni][0], 0.f) : 0.f;
                float v1 = k0v ? fmaxf(acc[mi][ni][1], 0.f) : 0.f;
                float v2 = k1v ? fmaxf(acc[mi][ni][2], 0.f) : 0.f;
                float v3 = k1v ? fmaxf(acc[mi][ni][3], 0.f) : 0.f;
                pmax[ni][0] = fmaxf(pmax[ni][0], fmaxf(v0, v2));
                pmax[ni][1] = fmaxf(pmax[ni][1], fmaxf(v1, v3));
                *(uint2*)(g_h2 + (size_t)(m0 + r) * 128 + c0) =
                    make_uint2(f2tf32(v0), f2tf32(v1));
                *(uint2*)(g_h2 + (size_t)(m0 + r + 8) * 128 + c0) =
                    make_uint2(f2tf32(v2), f2tf32(v3));
            }
        }
        #pragma unroll
        for (int ni = 0; ni < 8; ni++) {
            atomicMaxF_nonneg(&pl[wn + ni * 8 + 2 * tg], pmax[ni][0]);
            atomicMaxF_nonneg(&pl[wn + ni * 8 + 2 * tg + 1], pmax[ni][1]);
        }
    }
    __syncthreads();
    if (t < 128) atomicMaxF_nonneg(&g_pool[s * 128 + t], pl[t]);
    if (t == 0 && *vf) atomicOr(&g_valid[s], 1);
}

// ============================= kA2: c = b3 + pool @ W3_bot (fp32) ====================
__global__ void __launch_bounds__(256, 4)
kA2(const float* __restrict__ W3, const float* __restrict__ b3)
{
    __shared__ float ps[128];
    const int t = threadIdx.x, s = blockIdx.x;
    if (t < 128) ps[t] = g_pool[s * 128 + t];
    __syncthreads();
    float acc = b3[t];
    #pragma unroll 8
    for (int k = 0; k < 128; k++)
        acc += ps[k] * W3[(size_t)(128 + k) * D3 + t];
    g_c[s * D3 + t] = acc;
}

// =====================================================================================
// kBC (tf32, ldmatrix, cp.async): 256 threads, warp tiles 64x64 (2m x 4n warps).
// phase1: h3 = relu(h2 @ W3top^T(n-major) + c), M128 N256 K128, all operands smem.
// phase2: acc = h3 @ W4, K=256 via 8 cp.async double-buffered k32 chunks.
// smem words:
#define BC_R1   0        // 18432: h2s [128][132] (phase1) / W4 bufs 2x[256][36] (phase2)
#define BC_R2   18432    // 33792: w3s [256][132] (phase1) / h3s [128][260] (phase2)
#define BC_CV   52224    // 256
#define BC_B4   52480    // 256
#define BC_CM   52736    // 256
#define BC_MS   52992    // 128 (int)
#define BC_SMW  53120    // -> 212480 B
// =====================================================================================
__global__ void __launch_bounds__(256, 1)
kBC(const float* __restrict__ b4, const int* __restrict__ mask)
{
    extern __shared__ uint32_t smw[];
    uint32_t* h2s = smw + BC_R1;
    uint32_t* w3s = smw + BC_R2;
    uint32_t* h3s = smw + BC_R2;
    float* cv   = (float*)(smw + BC_CV);
    float* b4s  = (float*)(smw + BC_B4);
    float* cmax = (float*)(smw + BC_CM);
    int*   ms   = (int*)(smw + BC_MS);

    const int t = threadIdx.x;
    const int lane = t & 31, wid = t >> 5;
    const int g = lane >> 2, tg = lane & 3;
    const int wm = (wid & 1) * 64;          // 2 m-groups of 64
    const int wn = (wid >> 1) * 64;         // 4 n-groups of 64
    const int m0 = blockIdx.x * 128;
    const int s  = m0 >> 10;

    const uint32_t smb = (uint32_t)__cvta_generic_to_shared(smw);
    const uint32_t r1b = smb;                    // bytes
    const uint32_t r2b = smb + BC_R2 * 4;
    // per-thread ldmatrix lane offsets (words):
    //  A: lanes 0-7 tile(rows,k0), 8-15 (rows+8,k0), 16-23 (rows,k0+4), 24-31 (rows+8,k0+4)
    const int laneA = lane & 15, kselA = (lane >> 4) * 4;
    //  B (n-major): matrices = (n-group lo/hi) x (k halves)
    const int laneB = ((lane >> 4) << 3) + (lane & 7), kselB = ((lane >> 3) & 1) * 4;
    const uint32_t pA1 = (uint32_t)(laneA * 132 + kselA) * 4;
    const uint32_t pB1 = (uint32_t)(laneB * 132 + kselB) * 4;
    const uint32_t pA2 = (uint32_t)(laneA * 260 + kselA) * 4;
    const uint32_t pB2 = (uint32_t)(laneB * 36  + kselB) * 4;

    cv[t] = g_c[s * D3 + t]; b4s[t] = b4[t]; cmax[t] = 0.f;
    if (t < 128) ms[t] = (mask[m0 + t] != 0);

    #pragma unroll
    for (int j = 0; j < 16; j++) {     // h2s: 128x128 words
        int i = t + j * 256;
        int row = i >> 5, q4 = (i & 31) * 4;
        *(uint4*)(h2s + row * 132 + q4) =
            *(const uint4*)(g_h2 + (size_t)(m0 + row) * 128 + q4);
    }
    #pragma unroll
    for (int j = 0; j < 32; j++) {     // w3s: 256x128 words, n-major
        int i = t + j * 256;
        int n = i >> 5, q4 = (i & 31) * 4;
        *(uint4*)(w3s + n * 132 + q4) = *(const uint4*)(g_w3t + n * 128 + q4);
    }
    __syncthreads();

    // ---- phase1: 16 k8-steps, 32 mma each ----
    float acc[4][8][4];
    #pragma unroll
    for (int mi = 0; mi < 4; mi++)
        #pragma unroll
        for (int ni = 0; ni < 8; ni++) {
            float ca = cv[wn + ni * 8 + 2 * tg], cb = cv[wn + ni * 8 + 2 * tg + 1];
            acc[mi][ni][0] = ca; acc[mi][ni][1] = cb;
            acc[mi][ni][2] = ca; acc[mi][ni][3] = cb;
        }
    #pragma unroll 4
    for (int ks = 0; ks < 16; ks++) {
        const int k0 = ks * 8;
        uint32_t af[4][4], bf[4][4];
        #pragma unroll
        for (int mi = 0; mi < 4; mi++)
            ldsm4(af[mi], r1b + (uint32_t)(((wm + mi * 16) * 132 + k0) * 4) + pA1);
        #pragma unroll
        for (int p = 0; p < 4; p++)
            ldsm4(bf[p], r2b + (uint32_t)(((wn + p * 16) * 132 + k0) * 4) + pB1);
        #pragma unroll
        for (int mi = 0; mi < 4; mi++)
            #pragma unroll
            for (int ni = 0; ni < 8; ni++)
                mma_tf32(acc[mi][ni], af[mi], &bf[ni >> 1][(ni & 1) * 2]);
    }
    __syncthreads();   // all warps done reading h2s/w3s

    // issue W4 chunks 0,1 via cp.async into r1 bufs (h2s region is dead)
    {
        #pragma unroll
        for (int j = 0; j < 8; j++) {
            int i = t + j * 256;
            int n = i >> 3, q4 = (i & 7) * 4;
            cp_async16(r1b + (uint32_t)((n * 36 + q4) * 4), g_w4t + n * 256 + q4);
        }
        cp_commit();
        #pragma unroll
        for (int j = 0; j < 8; j++) {
            int i = t + j * 256;
            int n = i >> 3, q4 = (i & 7) * 4;
            cp_async16(r1b + (uint32_t)((9216 + n * 36 + q4) * 4), g_w4t + n * 256 + 32 + q4);
        }
        cp_commit();
    }

    // epilogue1: h3 (tf32) overwrites w3s region, [m][k] stride 260
    #pragma unroll
    for (int mi = 0; mi < 4; mi++) {
        const int R = wm + mi * 16;
        #pragma unroll
        for (int ni = 0; ni < 8; ni++) {
            int c0 = wn + ni * 8 + 2 * tg;
            *(uint2*)(h3s + (R + g) * 260 + c0) = make_uint2(
                f2tf32(fmaxf(acc[mi][ni][0], 0.f)), f2tf32(fmaxf(acc[mi][ni][1], 0.f)));
            *(uint2*)(h3s + (R + 8 + g) * 260 + c0) = make_uint2(
                f2tf32(fmaxf(acc[mi][ni][2], 0.f)), f2tf32(fmaxf(acc[mi][ni][3], 0.f)));
        }
    }
    __syncthreads();   // h3 visible

    // ---- phase2: 8 chunks of k=32, cp.async double-buffered ----
    float acc2[4][8][4];
    #pragma unroll
    for (int mi = 0; mi < 4; mi++)
        #pragma unroll
        for (int ni = 0; ni < 8; ni++) {
            float ba = b4s[wn + ni * 8 + 2 * tg], bb = b4s[wn + ni * 8 + 2 * tg + 1];
            acc2[mi][ni][0] = ba; acc2[mi][ni][1] = bb;
            acc2[mi][ni][2] = ba; acc2[mi][ni][3] = bb;
        }
    #pragma unroll 1
    for (int ch = 0; ch < 8; ++ch) {
        if (ch == 7) asm volatile("cp.async.wait_group 0;" ::: "memory");
        else         asm volatile("cp.async.wait_group 1;" ::: "memory");
        __syncthreads();
        const uint32_t bufb = r1b + (uint32_t)((ch & 1) * 9216 * 4);
        #pragma unroll
        for (int ks = 0; ks < 4; ks++) {
            const int k0 = ks * 8;
            uint32_t af[4][4], bf[4][4];
            #pragma unroll
            for (int mi = 0; mi < 4; mi++)
                ldsm4(af[mi], r2b + (uint32_t)(((wm + mi * 16) * 260 + ch * 32 + k0) * 4) + pA2);
            #pragma unroll
            for (int p = 0; p < 4; p++)
                ldsm4(bf[p], bufb + (uint32_t)(((wn + p * 16) * 36 + k0) * 4) + pB2);
            #pragma unroll
            for (int mi = 0; mi < 4; mi++)
                #pragma unroll
                for (int ni = 0; ni < 8; ni++)
                    mma_tf32(acc2[mi][ni], af[mi], &bf[ni >> 1][(ni & 1) * 2]);
        }
        if (ch < 6) {
            __syncthreads();   // all warps done reading buf[ch&1]
            #pragma unroll
            for (int j = 0; j < 8; j++) {
                int i = t + j * 256;
                int n = i >> 3, q4 = (i & 7) * 4;
                cp_async16(bufb + (uint32_t)((n * 36 + q4) * 4),
                           g_w4t + n * 256 + (ch + 2) * 32 + q4);
            }
            cp_commit();
        }
    }

    // ---- final epilogue: relu (b4 in acc), mask rows, col max ----
    #pragma unroll
    for (int ni = 0; ni < 8; ni++) {
        int c0 = wn + ni * 8 + 2 * tg;
        float mx0 = 0.f, mx1 = 0.f;
        #pragma unroll
        for (int mi = 0; mi < 4; mi++) {
            const int R = wm + mi * 16;
            const int k0v = ms[R + g], k1v = ms[R + 8 + g];
            float v0 = fmaxf(acc2[mi][ni][0], 0.f);
            float v1 = fmaxf(acc2[mi][ni][1], 0.f);
            float v2 = fmaxf(acc2[mi][ni][2], 0.f);
            float v3 = fmaxf(acc2[mi][ni][3], 0.f);
            if (k0v) { mx0 = fmaxf(mx0, v0); mx1 = fmaxf(mx1, v1); }
            if (k1v) { mx0 = fmaxf(mx0, v2); mx1 = fmaxf(mx1, v3); }
        }
        atomicMaxF_nonneg(&cmax[c0], mx0);
        atomicMaxF_nonneg(&cmax[c0 + 1], mx1);
    }
    __syncthreads();
    atomicMax((int*)&g_feat[s * D3 + t], __float_as_int(cmax[t]));
}

// ============================= kD: per-segment out MLP (fp32) ========================
__global__ void __launch_bounds__(256, 1)
kD(const float* __restrict__ Wo1, const float* __restrict__ bo1,
   const float* __restrict__ Wo2, const float* __restrict__ bo2,
   float* __restrict__ out)
{
    __shared__ float fs[D3], t1[D3];
    const int t = threadIdx.x, s = blockIdx.x;
    fs[t] = g_feat[s * D3 + t];
    __syncthreads();
    float a = bo1[t];
    #pragma unroll 8
    for (int k = 0; k < D3; k++) a += fs[k] * Wo1[k * D3 + t];
    t1[t] = fmaxf(a, 0.f);
    __syncthreads();
    float o = bo2[t];
    #pragma unroll 8
    for (int k = 0; k < D3; k++) o += t1[k] * Wo2[k * D3 + t];
    if (!g_valid[s]) o = 0.f;
    out[s * D3 + t] = o;
}

// =====================================================================================
extern "C" void kernel_launch(void* const* d_in, const int* in_sizes, int n_in,
                              void* d_out, int out_size)
{
    (void)in_sizes; (void)n_in; (void)out_size;
    const float* x   = (const float*)d_in[0];
    const int*   msk = (const int*)  d_in[1];
    const float* W1  = (const float*)d_in[2];
    const float* b1  = (const float*)d_in[3];
    const float* W2  = (const float*)d_in[4];
    const float* b2  = (const float*)d_in[5];
    const float* W3  = (const float*)d_in[6];
    const float* b3  = (const float*)d_in[7];
    const float* W4  = (const float*)d_in[8];
    const float* b4  = (const float*)d_in[9];
    const float* Wo1 = (const float*)d_in[10];
    const float* bo1 = (const float*)d_in[11];
    const float* Wo2 = (const float*)d_in[12];
    const float* bo2 = (const float*)d_in[13];
    float* out = (float*)d_out;

    uint32_t *w3t, *w4t;
    cudaGetSymbolAddress((void**)&w3t, g_w3t);
    cudaGetSymbolAddress((void**)&w4t, g_w4t);

    const size_t smA  = (size_t)A_SMW * 4;    //  99 KB
    const size_t smBC = (size_t)BC_SMW * 4;   // 212.5 KB

    cudaFuncSetAttribute(kA,  cudaFuncAttributeMaxDynamicSharedMemorySize, (int)smA);
    cudaFuncSetAttribute(kBC, cudaFuncAttributeMaxDynamicSharedMemorySize, (int)smBC);

    kZ<<<S_, 256>>>();
    kP<<<128, 256>>>(W3, w3t, 128, 256);   // W3 top half -> [n][k]
    kP<<<256, 256>>>(W4, w4t, 256, 256);   // W4 -> [n][k]
    kA <<<NPTS / 128, 256, smA>>>(x, msk, W1, b1, W2, b2);
    kA2<<<S_, 256>>>(W3, b3);
    kBC<<<NPTS / 128, 256, smBC>>>(b4, msk);
    kD <<<S_, 256>>>(Wo1, bo1, Wo2, bo2, out);
}

// round 8
// speedup vs baseline: 4.2364x; 1.0069x over previous
#include <cuda_runtime.h>
#include <cstdint>

#define S_  512      // B*T segments
#define P_  1024     // points per segment
#define D3  256
#define NPTS (S_ * P_)

// ---------------- global scratch ----------------
__device__ uint32_t g_h2[(size_t)NPTS * 128];  // masked h2 as tf32 bits (256 MB)
__device__ uint32_t g_w3t[256 * 128];          // W3 top, tf32, [n][k]
__device__ uint32_t g_w4t[256 * 256];          // W4, tf32, [n][k]
__device__ float g_pool[S_ * 128];
__device__ float g_c[S_ * D3];
__device__ float g_feat[S_ * D3];
__device__ int   g_valid[S_];

__device__ __forceinline__ void atomicMaxF_nonneg(float* addr, float v) {
    atomicMax((int*)addr, __float_as_int(v));   // valid for non-negative floats
}
__device__ __forceinline__ uint32_t f2tf32(float x) {
    uint32_t r; asm("cvt.rna.tf32.f32 %0, %1;" : "=r"(r) : "f"(x)); return r;
}
__device__ __forceinline__ void mma_tf32(float d[4], const uint32_t a[4], const uint32_t b[2]) {
    asm volatile(
        "mma.sync.aligned.m16n8k8.row.col.f32.tf32.tf32.f32 "
        "{%0,%1,%2,%3}, {%4,%5,%6,%7}, {%8,%9}, {%0,%1,%2,%3};\n"
        : "+f"(d[0]), "+f"(d[1]), "+f"(d[2]), "+f"(d[3])
        : "r"(a[0]), "r"(a[1]), "r"(a[2]), "r"(a[3]), "r"(b[0]), "r"(b[1]));
}
__device__ __forceinline__ void ldsm4(uint32_t d[4], uint32_t addr) {
    asm volatile("ldmatrix.sync.aligned.m8n8.x4.shared.b16 {%0,%1,%2,%3}, [%4];"
                 : "=r"(d[0]), "=r"(d[1]), "=r"(d[2]), "=r"(d[3]) : "r"(addr));
}
__device__ __forceinline__ void cp_async16(uint32_t saddr, const void* gaddr) {
    asm volatile("cp.async.cg.shared.global [%0], [%1], 16;"
                 :: "r"(saddr), "l"(gaddr) : "memory");
}
__device__ __forceinline__ void cp_commit() {
    asm volatile("cp.async.commit_group;" ::: "memory");
}

// ============================= kZ: zero the accumulators =============================
__global__ void kZ() {
    int i = blockIdx.x * 256 + threadIdx.x;     // grid 512 -> i < 131072
    g_feat[i] = 0.f;
    if (i < S_ * 128) g_pool[i] = 0.f;
    if (i < S_) g_valid[i] = 0;
}

// =========== kP: pack W (K x N f32 row-major) -> dst [n][k] tf32 words ==============
__global__ void kP(const float* __restrict__ W, uint32_t* __restrict__ dst, int K, int N) {
    int i = blockIdx.x * 256 + threadIdx.x;
    if (i >= K * N) return;
    int n = i % N, k = i / N;
    dst[n * K + k] = f2tf32(W[k * N + n]);
}

// =====================================================================================
// Kernel A (tf32 MMA): 128 points/CTA, grid 4096, 256 thr, shfl-based pool reduce.
#define A_XS  0        // [128][36]
#define A_W1  4608     // [32][72]
#define A_H1  6912     // [128][68]
#define A_W2  15616    // [64][136]
#define A_B1  24320    // 64
#define A_B2  24384    // 128
#define A_MS  24512    // 128 (int)
#define A_VF  24640    // 1
#define A_SMW 24641
// =====================================================================================
__global__ void __launch_bounds__(256, 2)
kA(const float* __restrict__ x, const int* __restrict__ mask,
   const float* __restrict__ W1, const float* __restrict__ b1,
   const float* __restrict__ W2, const float* __restrict__ b2)
{
    extern __shared__ uint32_t smw[];
    uint32_t* xs  = smw + A_XS;
    uint32_t* w1s = smw + A_W1;
    uint32_t* h1s = smw + A_H1;
    uint32_t* w2s = smw + A_W2;
    float* b1s = (float*)(smw + A_B1);
    float* b2s = (float*)(smw + A_B2);
    int*   ms  = (int*)(smw + A_MS);
    int*   vf  = (int*)(smw + A_VF);

    const int t = threadIdx.x;
    const int lane = t & 31, wid = t >> 5;
    const int g = lane >> 2, tg = lane & 3;
    const int m0 = blockIdx.x * 128;
    const int s  = m0 >> 10;

    {
        const int r = t >> 1, c16 = (t & 1) * 16;
        const float* gx = x + (size_t)(m0 + r) * 32 + c16;
        #pragma unroll
        for (int q = 0; q < 4; q++) {
            float4 v = *(const float4*)(gx + 4 * q);
            *(uint4*)(xs + r * 36 + c16 + 4 * q) =
                make_uint4(f2tf32(v.x), f2tf32(v.y), f2tf32(v.z), f2tf32(v.w));
        }
    }
    for (int i = t; i < 2048; i += 256) w1s[(i >> 6) * 72 + (i & 63)] = f2tf32(W1[i]);
    for (int i = t; i < 8192; i += 256) w2s[(i >> 7) * 136 + (i & 127)] = f2tf32(W2[i]);
    if (t < 64)  b1s[t] = b1[t];
    if (t < 128) b2s[t] = b2[t];
    if (t == 0)  *vf = 0;
    if (t < 128) {
        int mv = (mask[m0 + t] != 0);
        ms[t] = mv;
        if (mv) atomicOr(vf, 1);
    }
    __syncthreads();

    // h1 = relu(x@W1+b1): M128,N64,K32; warp tile 16x64
    {
        const int wm1 = wid * 16;
        float acc[8][4];
        #pragma unroll
        for (int ni = 0; ni < 8; ni++) {
            float ba = b1s[ni * 8 + 2 * tg], bb = b1s[ni * 8 + 2 * tg + 1];
            acc[ni][0] = ba; acc[ni][1] = bb; acc[ni][2] = ba; acc[ni][3] = bb;
        }
        #pragma unroll
        for (int k0 = 0; k0 < 32; k0 += 8) {
            uint32_t af[4];
            const int r = wm1 + g;
            af[0] = xs[r * 36 + k0 + tg];
            af[1] = xs[(r + 8) * 36 + k0 + tg];
            af[2] = xs[r * 36 + k0 + tg + 4];
            af[3] = xs[(r + 8) * 36 + k0 + tg + 4];
            uint32_t bf[8][2];
            #pragma unroll
            for (int ni = 0; ni < 8; ni++) {
                bf[ni][0] = w1s[(k0 + tg) * 72 + ni * 8 + g];
                bf[ni][1] = w1s[(k0 + tg + 4) * 72 + ni * 8 + g];
            }
            #pragma unroll
            for (int ni = 0; ni < 8; ni++) mma_tf32(acc[ni], af, bf[ni]);
        }
        const int r = wm1 + g;
        #pragma unroll
        for (int ni = 0; ni < 8; ni++) {
            int c0 = ni * 8 + 2 * tg;
            *(uint2*)(h1s + r * 68 + c0) = make_uint2(
                f2tf32(fmaxf(acc[ni][0], 0.f)), f2tf32(fmaxf(acc[ni][1], 0.f)));
            *(uint2*)(h1s + (r + 8) * 68 + c0) = make_uint2(
                f2tf32(fmaxf(acc[ni][2], 0.f)), f2tf32(fmaxf(acc[ni][3], 0.f)));
        }
    }
    __syncthreads();

    // h2 = relu(h1@W2+b2) mask store: M128,N128,K64; warp tile 32x64
    {
        const int wm = (wid & 3) * 32, wn = (wid >> 2) * 64;
        float acc[2][8][4];
        #pragma unroll
        for (int mi = 0; mi < 2; mi++)
            #pragma unroll
            for (int ni = 0; ni < 8; ni++) {
                float ba = b2s[wn + ni * 8 + 2 * tg], bb = b2s[wn + ni * 8 + 2 * tg + 1];
                acc[mi][ni][0] = ba; acc[mi][ni][1] = bb;
                acc[mi][ni][2] = ba; acc[mi][ni][3] = bb;
            }
        #pragma unroll
        for (int k0 = 0; k0 < 64; k0 += 8) {
            uint32_t af[2][4];
            #pragma unroll
            for (int mi = 0; mi < 2; mi++) {
                const int r = wm + mi * 16 + g;
                af[mi][0] = h1s[r * 68 + k0 + tg];
                af[mi][1] = h1s[(r + 8) * 68 + k0 + tg];
                af[mi][2] = h1s[r * 68 + k0 + tg + 4];
                af[mi][3] = h1s[(r + 8) * 68 + k0 + tg + 4];
            }
            uint32_t bf[8][2];
            #pragma unroll
            for (int ni = 0; ni < 8; ni++) {
                bf[ni][0] = w2s[(k0 + tg) * 136 + wn + ni * 8 + g];
                bf[ni][1] = w2s[(k0 + tg + 4) * 136 + wn + ni * 8 + g];
            }
            #pragma unroll
            for (int mi = 0; mi < 2; mi++)
                #pragma unroll
                for (int ni = 0; ni < 8; ni++) mma_tf32(acc[mi][ni], af[mi], bf[ni]);
        }
        float pmax[8][2];
        #pragma unroll
        for (int ni = 0; ni < 8; ni++) { pmax[ni][0] = 0.f; pmax[ni][1] = 0.f; }
        #pragma unroll
        for (int mi = 0; mi < 2; mi++) {
            const int r = wm + mi * 16 + g;
            const int k0v = ms[r], k1v = ms[r + 8];
            #pragma unroll
            for (int ni = 0; ni < 8; ni++) {
                int c0 = wn + ni * 8 + 2 * tg;
                float v0 = k0v ? fmaxf(acc[mi][ni][0], 0.f) : 0.f;
                float v1 = k0v ? fmaxf(acc[mi][ni][1], 0.f) : 0.f;
                float v2 = k1v ? fmaxf(acc[mi][ni][2], 0.f) : 0.f;
                float v3 = k1v ? fmaxf(acc[mi][ni][3], 0.f) : 0.f;
                pmax[ni][0] = fmaxf(pmax[ni][0], fmaxf(v0, v2));
                pmax[ni][1] = fmaxf(pmax[ni][1], fmaxf(v1, v3));
                *(uint2*)(g_h2 + (size_t)(m0 + r) * 128 + c0) =
                    make_uint2(f2tf32(v0), f2tf32(v1));
                *(uint2*)(g_h2 + (size_t)(m0 + r + 8) * 128 + c0) =
                    make_uint2(f2tf32(v2), f2tf32(v3));
            }
        }
        // pool reduce: shfl-max across g lanes, then one global atomic per col
        #pragma unroll
        for (int ni = 0; ni < 8; ni++) {
            float mx0 = pmax[ni][0], mx1 = pmax[ni][1];
            #pragma unroll
            for (int off = 4; off < 32; off <<= 1) {
                mx0 = fmaxf(mx0, __shfl_xor_sync(0xffffffffu, mx0, off));
                mx1 = fmaxf(mx1, __shfl_xor_sync(0xffffffffu, mx1, off));
            }
            if (g == 0) {
                atomicMaxF_nonneg(&g_pool[s * 128 + wn + ni * 8 + 2 * tg], mx0);
                atomicMaxF_nonneg(&g_pool[s * 128 + wn + ni * 8 + 2 * tg + 1], mx1);
            }
        }
    }
    if (t == 0 && *vf) atomicOr(&g_valid[s], 1);
}

// ============================= kA2: c = b3 + pool @ W3_bot (fp32) ====================
__global__ void __launch_bounds__(256, 4)
kA2(const float* __restrict__ W3, const float* __restrict__ b3)
{
    __shared__ float ps[128];
    const int t = threadIdx.x, s = blockIdx.x;
    if (t < 128) ps[t] = g_pool[s * 128 + t];
    __syncthreads();
    float acc = b3[t];
    #pragma unroll 8
    for (int k = 0; k < 128; k++)
        acc += ps[k] * W3[(size_t)(128 + k) * D3 + t];
    g_c[s * D3 + t] = acc;
}

// =====================================================================================
// kBC (tf32, ldmatrix, cp.async): 256 threads, warp tiles 64x64 (2m x 4n warps).
// phase1: h3 = relu(h2 @ W3top^T + c), staged: h2s/w3s stream in 4 k-stage cp.async
//         groups consumed as phase1 advances (startup load overlapped with mma).
// phase2: acc = h3 @ W4, K=256 via 8 cp.async double-buffered k32 chunks.
// smem words:
#define BC_R1   0        // 18432: h2s [128][132] (phase1) / W4 bufs 2x[256][36] (phase2)
#define BC_R2   18432    // 33792: w3s [256][132] (phase1) / h3s [128][260] (phase2)
#define BC_CV   52224    // 256
#define BC_B4   52480    // 256
#define BC_CM   52736    // 256
#define BC_MS   52992    // 128 (int)
#define BC_SMW  53120    // -> 212480 B
// =====================================================================================
__global__ void __launch_bounds__(256, 1)
kBC(const float* __restrict__ b4, const int* __restrict__ mask)
{
    extern __shared__ uint32_t smw[];
    uint32_t* h3s = smw + BC_R2;            // overlays w3s after phase1
    float* cv   = (float*)(smw + BC_CV);
    float* b4s  = (float*)(smw + BC_B4);
    float* cmax = (float*)(smw + BC_CM);
    int*   ms   = (int*)(smw + BC_MS);

    const int t = threadIdx.x;
    const int lane = t & 31, wid = t >> 5;
    const int g = lane >> 2, tg = lane & 3;
    const int wm = (wid & 1) * 64;          // 2 m-groups of 64
    const int wn = (wid >> 1) * 64;         // 4 n-groups of 64
    const int m0 = blockIdx.x * 128;
    const int s  = m0 >> 10;

    const uint32_t smb = (uint32_t)__cvta_generic_to_shared(smw);
    const uint32_t r1b = smb;                    // bytes
    const uint32_t r2b = smb + BC_R2 * 4;
    // ldmatrix lane offsets (bytes)
    const int laneA = lane & 15, kselA = (lane >> 4) * 4;
    const int laneB = ((lane >> 4) << 3) + (lane & 7), kselB = ((lane >> 3) & 1) * 4;
    const uint32_t pA1 = (uint32_t)(laneA * 132 + kselA) * 4;
    const uint32_t pB1 = (uint32_t)(laneB * 132 + kselB) * 4;
    const uint32_t pA2 = (uint32_t)(laneA * 260 + kselA) * 4;
    const uint32_t pB2 = (uint32_t)(laneB * 36  + kselB) * 4;

    // ---- staged cp.async load: 4 k-stages of (h2 32 words/row + w3 32 words/row) ----
    #pragma unroll
    for (int st = 0; st < 4; st++) {
        #pragma unroll
        for (int j = 0; j < 4; j++) {               // h2: 128 rows x 8 uint4
            int i = t + j * 256;
            int row = i >> 3, off = (i & 7) * 4;
            cp_async16(r1b + (uint32_t)((row * 132 + st * 32 + off) * 4),
                       g_h2 + (size_t)(m0 + row) * 128 + st * 32 + off);
        }
        #pragma unroll
        for (int j = 0; j < 8; j++) {               // w3: 256 rows x 8 uint4
            int i = t + j * 256;
            int n = i >> 3, off = (i & 7) * 4;
            cp_async16(r2b + (uint32_t)((n * 132 + st * 32 + off) * 4),
                       g_w3t + n * 128 + st * 32 + off);
        }
        cp_commit();
    }

    cv[t] = g_c[s * D3 + t]; b4s[t] = b4[t]; cmax[t] = 0.f;
    if (t < 128) ms[t] = (mask[m0 + t] != 0);

    // ---- phase1: 4 stages x 4 k8-steps, 32 mma each ----
    float acc[4][8][4];
    #pragma unroll
    for (int mi = 0; mi < 4; mi++)
        #pragma unroll
        for (int ni = 0; ni < 8; ni++)
            #pragma unroll
            for (int q = 0; q < 4; q++) acc[mi][ni][q] = 0.f;

    #pragma unroll
    for (int stg = 0; stg < 4; stg++) {
        if      (stg == 0) asm volatile("cp.async.wait_group 3;" ::: "memory");
        else if (stg == 1) asm volatile("cp.async.wait_group 2;" ::: "memory");
        else if (stg == 2) asm volatile("cp.async.wait_group 1;" ::: "memory");
        else               asm volatile("cp.async.wait_group 0;" ::: "memory");
        __syncthreads();
        #pragma unroll
        for (int kss = 0; kss < 4; kss++) {
            const int k0 = stg * 32 + kss * 8;
            uint32_t af[4][4], bf[4][4];
            #pragma unroll
            for (int mi = 0; mi < 4; mi++)
                ldsm4(af[mi], r1b + (uint32_t)(((wm + mi * 16) * 132 + k0) * 4) + pA1);
            #pragma unroll
            for (int p = 0; p < 4; p++)
                ldsm4(bf[p], r2b + (uint32_t)(((wn + p * 16) * 132 + k0) * 4) + pB1);
            #pragma unroll
            for (int mi = 0; mi < 4; mi++)
                #pragma unroll
                for (int ni = 0; ni < 8; ni++)
                    mma_tf32(acc[mi][ni], af[mi], &bf[ni >> 1][(ni & 1) * 2]);
        }
    }
    __syncthreads();   // all warps done reading h2s/w3s

    // issue W4 chunks 0,1 via cp.async into r1 bufs (h2s region is dead)
    {
        #pragma unroll
        for (int j = 0; j < 8; j++) {
            int i = t + j * 256;
            int n = i >> 3, q4 = (i & 7) * 4;
            cp_async16(r1b + (uint32_t)((n * 36 + q4) * 4), g_w4t + n * 256 + q4);
        }
        cp_commit();
        #pragma unroll
        for (int j = 0; j < 8; j++) {
            int i = t + j * 256;
            int n = i >> 3, q4 = (i & 7) * 4;
            cp_async16(r1b + (uint32_t)((9216 + n * 36 + q4) * 4), g_w4t + n * 256 + 32 + q4);
        }
        cp_commit();
    }

    // epilogue1: h3 = relu(acc + c) (tf32) overwrites w3s region, [m][k] stride 260
    #pragma unroll
    for (int mi = 0; mi < 4; mi++) {
        const int R = wm + mi * 16;
        #pragma unroll
        for (int ni = 0; ni < 8; ni++) {
            int c0 = wn + ni * 8 + 2 * tg;
            float ca = cv[c0], cb = cv[c0 + 1];
            *(uint2*)(h3s + (R + g) * 260 + c0) = make_uint2(
                f2tf32(fmaxf(acc[mi][ni][0] + ca, 0.f)),
                f2tf32(fmaxf(acc[mi][ni][1] + cb, 0.f)));
            *(uint2*)(h3s + (R + 8 + g) * 260 + c0) = make_uint2(
                f2tf32(fmaxf(acc[mi][ni][2] + ca, 0.f)),
                f2tf32(fmaxf(acc[mi][ni][3] + cb, 0.f)));
        }
    }
    __syncthreads();   // h3 visible

    // ---- phase2: 8 chunks of k=32, cp.async double-buffered ----
    float acc2[4][8][4];
    #pragma unroll
    for (int mi = 0; mi < 4; mi++)
        #pragma unroll
        for (int ni = 0; ni < 8; ni++) {
            float ba = b4s[wn + ni * 8 + 2 * tg], bb = b4s[wn + ni * 8 + 2 * tg + 1];
            acc2[mi][ni][0] = ba; acc2[mi][ni][1] = bb;
            acc2[mi][ni][2] = ba; acc2[mi][ni][3] = bb;
        }
    #pragma unroll 1
    for (int ch = 0; ch < 8; ++ch) {
        if (ch == 7) asm volatile("cp.async.wait_group 0;" ::: "memory");
        else         asm volatile("cp.async.wait_group 1;" ::: "memory");
        __syncthreads();
        const uint32_t bufb = r1b + (uint32_t)((ch & 1) * 9216 * 4);
        #pragma unroll
        for (int ks = 0; ks < 4; ks++) {
            const int k0 = ks * 8;
            uint32_t af[4][4], bf[4][4];
            #pragma unroll
            for (int mi = 0; mi < 4; mi++)
                ldsm4(af[mi], r2b + (uint32_t)(((wm + mi * 16) * 260 + ch * 32 + k0) * 4) + pA2);
            #pragma unroll
            for (int p = 0; p < 4; p++)
                ldsm4(bf[p], bufb + (uint32_t)(((wn + p * 16) * 36 + k0) * 4) + pB2);
            #pragma unroll
            for (int mi = 0; mi < 4; mi++)
                #pragma unroll
                for (int ni = 0; ni < 8; ni++)
                    mma_tf32(acc2[mi][ni], af[mi], &bf[ni >> 1][(ni & 1) * 2]);
        }
        if (ch < 6) {
            __syncthreads();   // all warps done reading buf[ch&1]
            #pragma unroll
            for (int j = 0; j < 8; j++) {
                int i = t + j * 256;
                int n = i >> 3, q4 = (i & 7) * 4;
                cp_async16(bufb + (uint32_t)((n * 36 + q4) * 4),
                           g_w4t + n * 256 + (ch + 2) * 32 + q4);
            }
            cp_commit();
        }
    }

    // ---- final epilogue: relu (b4 in acc), mask rows, col max ----
    #pragma unroll
    for (int ni = 0; ni < 8; ni++) {
        int c0 = wn + ni * 8 + 2 * tg;
        float mx0 = 0.f, mx1 = 0.f;
        #pragma unroll
        for (int mi = 0; mi < 4; mi++) {
            const int R = wm + mi * 16;
            const int k0v = ms[R + g], k1v = ms[R + 8 + g];
            float v0 = fmaxf(acc2[mi][ni][0], 0.f);
            float v1 = fmaxf(acc2[mi][ni][1], 0.f);
            float v2 = fmaxf(acc2[mi][ni][2], 0.f);
            float v3 = fmaxf(acc2[mi][ni][3], 0.f);
            if (k0v) { mx0 = fmaxf(mx0, v0); mx1 = fmaxf(mx1, v1); }
            if (k1v) { mx0 = fmaxf(mx0, v2); mx1 = fmaxf(mx1, v3); }
        }
        atomicMaxF_nonneg(&cmax[c0], mx0);
        atomicMaxF_nonneg(&cmax[c0 + 1], mx1);
    }
    __syncthreads();
    atomicMax((int*)&g_feat[s * D3 + t], __float_as_int(cmax[t]));
}

// ============ kD: out MLP, 8 segments/CTA, weights read once per CTA =================
__global__ void __launch_bounds__(256, 2)
kD(const float* __restrict__ Wo1, const float* __restrict__ bo1,
   const float* __restrict__ Wo2, const float* __restrict__ bo2,
   float* __restrict__ out)
{
    __shared__ float fs[8][256], t1[8][256];
    __shared__ int vld[8];
    const int t = threadIdx.x, s0 = blockIdx.x * 8;
    for (int i = t; i < 8 * 256; i += 256)
        fs[i >> 8][i & 255] = g_feat[(s0 + (i >> 8)) * 256 + (i & 255)];
    if (t < 8) vld[t] = g_valid[s0 + t];
    __syncthreads();
    float a[8];
    #pragma unroll
    for (int e = 0; e < 8; e++) a[e] = bo1[t];
    for (int k = 0; k < 256; k += 4) {
        #pragma unroll
        for (int kk = 0; kk < 4; kk++) {
            float w = Wo1[(k + kk) * 256 + t];
            #pragma unroll
            for (int e = 0; e < 8; e++) a[e] += fs[e][k + kk] * w;
        }
    }
    #pragma unroll
    for (int e = 0; e < 8; e++) t1[e][t] = fmaxf(a[e], 0.f);
    __syncthreads();
    #pragma unroll
    for (int e = 0; e < 8; e++) a[e] = bo2[t];
    for (int k = 0; k < 256; k += 4) {
        #pragma unroll
        for (int kk = 0; kk < 4; kk++) {
            float w = Wo2[(k + kk) * 256 + t];
            #pragma unroll
            for (int e = 0; e < 8; e++) a[e] += t1[e][k + kk] * w;
        }
    }
    #pragma unroll
    for (int e = 0; e < 8; e++)
        out[(s0 + e) * 256 + t] = vld[e] ? a[e] : 0.f;
}

// =====================================================================================
extern "C" void kernel_launch(void* const* d_in, const int* in_sizes, int n_in,
                              void* d_out, int out_size)
{
    (void)in_sizes; (void)n_in; (void)out_size;
    const float* x   = (const float*)d_in[0];
    const int*   msk = (const int*)  d_in[1];
    const float* W1  = (const float*)d_in[2];
    const float* b1  = (const float*)d_in[3];
    const float* W2  = (const float*)d_in[4];
    const float* b2  = (const float*)d_in[5];
    const float* W3  = (const float*)d_in[6];
    const float* b3  = (const float*)d_in[7];
    const float* W4  = (const float*)d_in[8];
    const float* b4  = (const float*)d_in[9];
    const float* Wo1 = (const float*)d_in[10];
    const float* bo1 = (const float*)d_in[11];
    const float* Wo2 = (const float*)d_in[12];
    const float* bo2 = (const float*)d_in[13];
    float* out = (float*)d_out;

    uint32_t *w3t, *w4t;
    cudaGetSymbolAddress((void**)&w3t, g_w3t);
    cudaGetSymbolAddress((void**)&w4t, g_w4t);

    const size_t smA  = (size_t)A_SMW * 4;    //  98.6 KB
    const size_t smBC = (size_t)BC_SMW * 4;   // 212.5 KB

    cudaFuncSetAttribute(kA,  cudaFuncAttributeMaxDynamicSharedMemorySize, (int)smA);
    cudaFuncSetAttribute(kBC, cudaFuncAttributeMaxDynamicSharedMemorySize, (int)smBC);

    kZ<<<S_, 256>>>();
    kP<<<128, 256>>>(W3, w3t, 128, 256);   // W3 top half -> [n][k]
    kP<<<256, 256>>>(W4, w4t, 256, 256);   // W4 -> [n][k]
    kA <<<NPTS / 128, 256, smA>>>(x, msk, W1, b1, W2, b2);
    kA2<<<S_, 256>>>(W3, b3);
    kBC<<<NPTS / 128, 256, smBC>>>(b4, msk);
    kD <<<64, 256>>>(Wo1, bo1, Wo2, bo2, out);
}